// round 12
// baseline (speedup 1.0000x reference)
#include <cuda_runtime.h>
#include <cuda_fp16.h>
#include <math.h>
#include <stdint.h>

// ---------------- problem constants ----------------
#define NB_    56
#define L_     (NB_*NB_)       // 3136
#define NBATCH 16
#define DIM    384
#define DI     768
#define HG2    1536
#define MLPD   1536
#define MTOT   (NBATCH*L_)     // 50176

#define SCHUNK 64
#define SNCH   (L_/SCHUNK)     // 49

// ---------------- scratch ----------------
__device__ __half  g_hln [(size_t)MTOT*DIM];
__device__ __half  g_hc  [(size_t)MTOT*DIM];
__device__ __half2 g_cv1 [(size_t)MTOT*DI];    // (c,v) pairs per channel
__device__ __half2 g_cv2 [(size_t)MTOT*DI];
__device__ __half  g_hs1 [(size_t)MTOT*DI];
__device__ __half  g_hs2 [(size_t)MTOT*DI];
__device__ float   g_hmid[(size_t)MTOT*DIM];
__device__ __half  g_mn  [(size_t)MTOT*DIM];
__device__ __half  g_m1  [(size_t)MTOT*MLPD];
__device__ __half  g_w1p [HG2*DIM];   // [1536][384] K-major, (h,g) col-interleaved
__device__ __half  g_w2p [HG2*DIM];
__device__ __half  g_wo1t[DIM*DI];    // [384][768]
__device__ __half  g_wo2t[DIM*DI];
__device__ __half  g_p1t [MLPD*DIM];  // [1536][384]
__device__ __half  g_p2t [DIM*MLPD];  // [384][1536]
__device__ float2  g_sum[(size_t)2*NBATCH*DI*SNCH];  // chunk summaries / h_in

// ---------------- helpers ----------------
__device__ __forceinline__ uint32_t smem_u32(const void* p) {
    uint32_t a;
    asm("{ .reg .u64 t; cvta.to.shared.u64 t, %1; cvt.u32.u64 %0, t; }"
        : "=r"(a) : "l"(p));
    return a;
}
#define CP_ASYNC16(sa, gp) \
    asm volatile("cp.async.cg.shared.global [%0], [%1], 16;" :: "r"(sa), "l"(gp))

__device__ __forceinline__ void mma_f16(float* d, const uint32_t* a,
                                        uint32_t b0, uint32_t b1) {
    asm volatile(
        "mma.sync.aligned.m16n8k16.row.col.f32.f16.f16.f32 "
        "{%0,%1,%2,%3}, {%4,%5,%6,%7}, {%8,%9}, {%0,%1,%2,%3};"
        : "+f"(d[0]), "+f"(d[1]), "+f"(d[2]), "+f"(d[3])
        : "r"(a[0]), "r"(a[1]), "r"(a[2]), "r"(a[3]), "r"(b0), "r"(b1));
}
__device__ __forceinline__ void ldsm_x4(uint32_t* r, uint32_t addr) {
    asm volatile("ldmatrix.sync.aligned.m8n8.x4.shared.b16 {%0,%1,%2,%3}, [%4];"
        : "=r"(r[0]), "=r"(r[1]), "=r"(r[2]), "=r"(r[3]) : "r"(addr));
}
// fast sigmoid(-x) = 1/(1+exp(x)) via MUFU.EX2 + MUFU.RCP (~2e-7 rel err)
__device__ __forceinline__ float fsign(float x) {
    return __fdividef(1.0f, 1.0f + __expf(x));
}

// ---------------- LayerNorm (fp32 in, fp16 out) ----------------
__global__ void ln_k(const float* __restrict__ x, const float* __restrict__ w,
                     const float* __restrict__ b, __half* __restrict__ o) {
    const int row = blockIdx.x;
    const int t = threadIdx.x;
    const float* xr = x + (size_t)row * DIM;
    float v0 = xr[t], v1 = xr[t + 128], v2 = xr[t + 256];
    float s = v0 + v1 + v2;
    float q = v0 * v0 + v1 * v1 + v2 * v2;
#pragma unroll
    for (int off = 16; off; off >>= 1) {
        s += __shfl_down_sync(0xffffffffu, s, off);
        q += __shfl_down_sync(0xffffffffu, q, off);
    }
    __shared__ float ss[4], qq[4];
    __shared__ float mu_s, rs_s;
    const int wid = t >> 5, ln = t & 31;
    if (ln == 0) { ss[wid] = s; qq[wid] = q; }
    __syncthreads();
    if (t == 0) {
        float S = ss[0] + ss[1] + ss[2] + ss[3];
        float Q = qq[0] + qq[1] + qq[2] + qq[3];
        float mu = S * (1.0f / DIM);
        float var = fmaxf(Q * (1.0f / DIM) - mu * mu, 0.0f);
        mu_s = mu;
        rs_s = rsqrtf(var + 1e-5f);
    }
    __syncthreads();
    const float mu = mu_s, rs = rs_s;
    __half* orow = o + (size_t)row * DIM;
    orow[t]       = __float2half_rn((v0 - mu) * rs * w[t]       + b[t]);
    orow[t + 128] = __float2half_rn((v1 - mu) * rs * w[t + 128] + b[t + 128]);
    orow[t + 256] = __float2half_rn((v2 - mu) * rs * w[t + 256] + b[t + 256]);
}

// ---------------- depthwise 3x3 conv (half in, half out, fp32 accum) ---------
__global__ void dwconv_k(const __half* __restrict__ x, const float* __restrict__ w,
                         const float* __restrict__ b, __half* __restrict__ o) {
    const int t = blockIdx.x;
    const int d = threadIdx.x;
    const int n = t / L_;
    const int l = t - n * L_;
    const int r = l / NB_, c = l - r * NB_;
    float acc = b[d];
    const float* wr = w + d * 9;
#pragma unroll
    for (int dr = -1; dr <= 1; ++dr) {
        const int rr = r + dr;
        if (rr < 0 || rr >= NB_) continue;
#pragma unroll
        for (int dc = -1; dc <= 1; ++dc) {
            const int cc = c + dc;
            if (cc < 0 || cc >= NB_) continue;
            acc += __half2float(x[((size_t)(n * L_ + rr * NB_ + cc)) * DIM + d]) *
                   wr[(dr + 1) * 3 + (dc + 1)];
        }
    }
    o[(size_t)t * DIM + d] = __float2half_rn(acc);
}

// ---------------- weight prep: transpose to K-major + half -------------------
__global__ void prep_w_k(const float* __restrict__ g1, const float* __restrict__ g2,
                         const float* __restrict__ wo1, const float* __restrict__ wo2,
                         const float* __restrict__ p1, const float* __restrict__ p2) {
    const int stride = gridDim.x * blockDim.x;
    const int i0 = blockIdx.x * blockDim.x + threadIdx.x;
    for (int i = i0; i < HG2 * DIM; i += stride) {
        const int j = i / DIM, k = i - j * DIM;
        const int src = k * HG2 + (j >> 1) + (j & 1) * DI;
        g_w1p[i] = __float2half_rn(g1[src]);
        g_w2p[i] = __float2half_rn(g2[src]);
    }
    for (int i = i0; i < DIM * DI; i += stride) {
        const int n = i / DI, k = i - n * DI;
        g_wo1t[i] = __float2half_rn(wo1[(size_t)k * DIM + n]);
        g_wo2t[i] = __float2half_rn(wo2[(size_t)k * DIM + n]);
    }
    for (int i = i0; i < MLPD * DIM; i += stride) {
        const int n = i / DIM, k = i - n * DIM;
        g_p1t[i] = __float2half_rn(p1[(size_t)k * MLPD + n]);
    }
    for (int i = i0; i < DIM * MLPD; i += stride) {
        const int n = i / MLPD, k = i - n * MLPD;
        g_p2t[i] = __float2half_rn(p2[(size_t)k * DIM + n]);
    }
}

// ---------------- chunked parallel minGRU scans (half2 cv) -------------------
__global__ void scan1_k() {
    const int gid = blockIdx.x * blockDim.x + threadIdx.x;
    const int ch = gid % DI;
    int r = gid / DI;
    const int j = r % SNCH; r /= SNCH;
    const int n = r % NBATCH;
    const int dir = r / NBATCH;
    const __half2* cv = dir ? g_cv2 : g_cv1;
    const size_t base = (size_t)n * L_ * DI + ch;
    int l = dir ? (L_ - 1 - j * SCHUNK) : j * SCHUNK;
    const int step = dir ? -1 : 1;
    float C = 1.0f, h = 0.0f;
#pragma unroll 4
    for (int i = 0; i < SCHUNK; ++i) {
        const float2 t = __half22float2(cv[base + (size_t)l * DI]);
        C *= t.x;
        h = fmaf(h, t.x, t.y);
        l += step;
    }
    g_sum[((size_t)((dir * NBATCH + n) * DI + ch)) * SNCH + j] = make_float2(C, h);
}

__global__ void scan2_k() {
    const int gid = blockIdx.x * blockDim.x + threadIdx.x;
    const int ch = gid % DI;
    int r = gid / DI;
    const int n = r % NBATCH;
    const int dir = r / NBATCH;
    float2* srow = g_sum + ((size_t)((dir * NBATCH + n) * DI + ch)) * SNCH;
    float h = 0.0f;
#pragma unroll 7
    for (int j = 0; j < SNCH; ++j) {
        const float2 s = srow[j];
        srow[j].x = h;                       // h_in for chunk j
        h = fmaf(h, s.x, s.y);
    }
}

__global__ void scan3_k() {
    const int gid = blockIdx.x * blockDim.x + threadIdx.x;
    const int ch = gid % DI;
    int r = gid / DI;
    const int j = r % SNCH; r /= SNCH;
    const int n = r % NBATCH;
    const int dir = r / NBATCH;
    const __half2* cv = dir ? g_cv2 : g_cv1;
    __half* hs = dir ? g_hs2 : g_hs1;
    const size_t base = (size_t)n * L_ * DI + ch;
    int l = dir ? (L_ - 1 - j * SCHUNK) : j * SCHUNK;
    const int step = dir ? -1 : 1;
    float h = g_sum[((size_t)((dir * NBATCH + n) * DI + ch)) * SNCH + j].x;
#pragma unroll 4
    for (int i = 0; i < SCHUNK; ++i) {
        const float2 t = __half22float2(cv[base + (size_t)l * DI]);
        h = fmaf(h, t.x, t.y);
        hs[base + (size_t)l * DI] = __float2half_rn(h);
        l += step;
    }
}

// --------- f16 mma.sync GEMM: 64x128x64 CTA tile, warp 32x32, 3-stage --------
#define TS2     72                         // halfs per smem row (64 + 8 pad)
#define AROWS   64
#define BROWS   128
#define TILEA   (AROWS * TS2)              // halfs, A region
#define STG_H   ((AROWS + BROWS) * TS2)    // halfs per stage = 13824
#define STAGE_B (STG_H * 2)                // bytes per stage = 27648
#define NSTG    3
#define DYNSMEM (NSTG * STAGE_B)           // 82944

#define EPI_CV      0
#define EPI_RES     1
#define EPI_GELU    2
#define EPI_BIASRES 3

template <int EPI>
__global__ void __launch_bounds__(256, 2)
tgemm_k(const __half* __restrict__ A1, const __half* __restrict__ B1, int K1,
        const __half* __restrict__ A2, const __half* __restrict__ B2, int K2,
        int N, const float* __restrict__ bias, const float* __restrict__ res,
        void* __restrict__ Cv) {
    extern __shared__ __half dynsmem[];
    const int tid = threadIdx.x;
    const int wid = tid >> 5, lane = tid & 31;
    const int g = lane >> 2, t = lane & 3;
    const int wm = (wid & 1) * 32, wn = (wid >> 1) * 32;   // 2m x 4n warps
    const int bn = blockIdx.x, bm = blockIdx.y;
    const uint32_t sbase = smem_u32(dynsmem);

    // per-lane ldmatrix base offsets (bytes, within a stage)
    const int lj = lane >> 3, li = lane & 7;
    const uint32_t aoff =
        (uint32_t)(((wm + (lj & 1) * 8 + li) * TS2 + (lj >> 1) * 8) * 2);
    const uint32_t boff =
        (uint32_t)((TILEA + (wn + (lj & 1) * 8 + li) * TS2 + (lj >> 1) * 8) * 2);

    const int KT1 = K1 >> 6;
    const int KT = KT1 + (K2 >> 6);

    // hoisted per-thread global pointers (advance by 64 per k-tile)
    const int grow = tid >> 3;               // 0..31
    const int gcol = (tid & 7) * 8;          // fixed 8-half segment
    const __half* pA = A1 + (size_t)(bm * AROWS + grow) * K1 + gcol;
    const __half* pB = B1 + (size_t)(bn * BROWS + grow) * K1 + gcol;
    size_t str = (size_t)32 * K1;            // 32-row stride
    // smem per-thread store offsets (fixed)
    const uint32_t ssA = (uint32_t)(grow * TS2 + gcol) * 2;
    const uint32_t ssB = (uint32_t)(TILEA + grow * TS2 + gcol) * 2;

    float acc[2][4][4];
#pragma unroll
    for (int mt = 0; mt < 2; mt++)
#pragma unroll
        for (int nt = 0; nt < 4; nt++)
#pragma unroll
            for (int i = 0; i < 4; i++) acc[mt][nt][i] = 0.0f;

    int next_load = 0;
    // prologue: fully issue the first two stages (pipeline fill)
#pragma unroll
    for (int pl = 0; pl < 2; ++pl) {
        if (pl < KT) {
            if (next_load == KT1 && A2) {
                pA = A2 + (size_t)(bm * AROWS + grow) * K2 + gcol;
                pB = B2 + (size_t)(bn * BROWS + grow) * K2 + gcol;
                str = (size_t)32 * K2;
            }
            const uint32_t sa = sbase + (next_load % NSTG) * STAGE_B;
#pragma unroll
            for (int i = 0; i < 2; ++i)
                CP_ASYNC16(sa + ssA + i * (32 * TS2 * 2), pA + i * str);
#pragma unroll
            for (int i = 0; i < 4; ++i)
                CP_ASYNC16(sa + ssB + i * (32 * TS2 * 2), pB + i * str);
            asm volatile("cp.async.commit_group;" ::: "memory");
            pA += 64; pB += 64;
            ++next_load;
        }
    }

    for (int kt = 0; kt < KT; ++kt) {
        if (kt + 1 < KT)
            asm volatile("cp.async.wait_group 1;" ::: "memory");
        else
            asm volatile("cp.async.wait_group 0;" ::: "memory");
        __syncthreads();

        // prefetch state for tile kt+2, interleaved into the MMA loop
        const bool pref = (next_load < KT);
        uint32_t spref = 0;
        if (pref) {
            if (next_load == KT1 && A2) {   // switch to second source
                pA = A2 + (size_t)(bm * AROWS + grow) * K2 + gcol;
                pB = B2 + (size_t)(bn * BROWS + grow) * K2 + gcol;
                str = (size_t)32 * K2;
            }
            spref = sbase + (next_load % NSTG) * STAGE_B;
        }

        const uint32_t sa = sbase + (kt % NSTG) * STAGE_B;
        const uint32_t abase = sa + aoff;
        const uint32_t bbase = sa + boff;
#pragma unroll
        for (int ks = 0; ks < 4; ++ks) {
            const uint32_t ko = (uint32_t)(ks * 32);   // 16 halfs = 32 bytes
            uint32_t af[2][4], bf[2][4];
#pragma unroll
            for (int mt = 0; mt < 2; ++mt)
                ldsm_x4(af[mt], abase + mt * (16 * TS2 * 2) + ko);
#pragma unroll
            for (int q = 0; q < 2; ++q)
                ldsm_x4(bf[q], bbase + q * (16 * TS2 * 2) + ko);
            if (pref) {   // 6 copies spread over 4 ks steps
                if (ks == 0) {
                    CP_ASYNC16(spref + ssA, pA);
                    CP_ASYNC16(spref + ssA + 32 * TS2 * 2, pA + str);
                } else if (ks == 1) {
                    CP_ASYNC16(spref + ssB, pB);
                    CP_ASYNC16(spref + ssB + 32 * TS2 * 2, pB + str);
                } else if (ks == 2) {
                    CP_ASYNC16(spref + ssB + 64 * TS2 * 2, pB + 2 * str);
                } else {
                    CP_ASYNC16(spref + ssB + 96 * TS2 * 2, pB + 3 * str);
                }
            }
#pragma unroll
            for (int mt = 0; mt < 2; ++mt)
#pragma unroll
                for (int nt = 0; nt < 4; ++nt)
                    mma_f16(acc[mt][nt], af[mt],
                            bf[nt >> 1][nt & 1], bf[nt >> 1][(nt & 1) + 2]);
        }
        if (pref) {
            asm volatile("cp.async.commit_group;" ::: "memory");
            pA += 64; pB += 64;
            ++next_load;
        }
    }

    // ---------------- fused epilogue (fast-math, direct paired stores) -------
#pragma unroll
    for (int mt = 0; mt < 2; ++mt) {
#pragma unroll
        for (int nt = 0; nt < 4; ++nt) {
            const int col = bn * BROWS + wn + nt * 8 + 2 * t;
            const int r0 = bm * AROWS + wm + mt * 16 + g;
#pragma unroll
            for (int h = 0; h < 2; ++h) {
                const int row = r0 + h * 8;
                const float v0 = acc[mt][nt][2 * h + 0];
                const float v1 = acc[mt][nt][2 * h + 1];
                const size_t idx = (size_t)row * N + col;
                if (EPI == EPI_CV) {
                    // (v0, v1) = (hidden, gate); c = sigmoid(-gate),
                    // tilde_h = h+0.5 (h>=0) else sigmoid(h); v = (1-c)*tilde_h
                    __half2* C = (__half2*)Cv;
                    const float cc = fsign(v1);          // sigmoid(-v1)
                    const float zz = 1.0f - cc;
                    const float sp = fsign(-v0);         // sigmoid(v0)
                    const float tld = (v0 >= 0.0f) ? (v0 + 0.5f) : sp;
                    C[idx >> 1] = __floats2half2_rn(cc, zz * tld);
                } else if (EPI == EPI_RES) {
                    float* C = (float*)Cv;
                    const float2 r = *(const float2*)&res[idx];
                    *(float2*)&C[idx] = make_float2(v0 + r.x, v1 + r.y);
                } else if (EPI == EPI_GELU) {
                    __half* C = (__half*)Cv;
                    const float2 b = *(const float2*)&bias[col];
                    const float t0 = v0 + b.x, t1 = v1 + b.y;
                    const float g0 = 0.5f * t0 * (1.0f + erff(t0 * 0.70710678f));
                    const float g1 = 0.5f * t1 * (1.0f + erff(t1 * 0.70710678f));
                    *(__half2*)&C[idx] = __floats2half2_rn(g0, g1);
                } else { // EPI_BIASRES
                    float* C = (float*)Cv;
                    const float2 r = *(const float2*)&res[idx];
                    const float2 b = *(const float2*)&bias[col];
                    *(float2*)&C[idx] = make_float2(v0 + b.x + r.x, v1 + b.y + r.y);
                }
            }
        }
    }
}

// ---------------- launch sequence ----------------
extern "C" void kernel_launch(void* const* d_in, const int* in_sizes, int n_in,
                              void* d_out, int out_size) {
    const float* x       = (const float*)d_in[0];
    const float* norm_w  = (const float*)d_in[1];
    const float* norm_b  = (const float*)d_in[2];
    const float* dw_w    = (const float*)d_in[3];
    const float* dw_b    = (const float*)d_in[4];
    const float* g1_whg  = (const float*)d_in[5];
    const float* g1_wout = (const float*)d_in[6];
    const float* g2_whg  = (const float*)d_in[7];
    const float* g2_wout = (const float*)d_in[8];
    const float* n2_w    = (const float*)d_in[9];
    const float* n2_b    = (const float*)d_in[10];
    const float* p1_w    = (const float*)d_in[11];
    const float* p1_b    = (const float*)d_in[12];
    const float* p2_w    = (const float*)d_in[13];
    const float* p2_b    = (const float*)d_in[14];
    float* out = (float*)d_out;

    float *hmid;
    __half2 *cv1, *cv2;
    __half *hln, *hc, *hs1, *hs2, *mn, *m1, *w1p, *w2p, *wo1t, *wo2t, *p1t, *p2t;
    cudaGetSymbolAddress((void**)&hln,  g_hln);
    cudaGetSymbolAddress((void**)&hc,   g_hc);
    cudaGetSymbolAddress((void**)&cv1,  g_cv1);
    cudaGetSymbolAddress((void**)&cv2,  g_cv2);
    cudaGetSymbolAddress((void**)&hs1,  g_hs1);
    cudaGetSymbolAddress((void**)&hs2,  g_hs2);
    cudaGetSymbolAddress((void**)&hmid, g_hmid);
    cudaGetSymbolAddress((void**)&mn,   g_mn);
    cudaGetSymbolAddress((void**)&m1,   g_m1);
    cudaGetSymbolAddress((void**)&w1p,  g_w1p);
    cudaGetSymbolAddress((void**)&w2p,  g_w2p);
    cudaGetSymbolAddress((void**)&wo1t, g_wo1t);
    cudaGetSymbolAddress((void**)&wo2t, g_wo2t);
    cudaGetSymbolAddress((void**)&p1t,  g_p1t);
    cudaGetSymbolAddress((void**)&p2t,  g_p2t);

    cudaFuncSetAttribute(tgemm_k<EPI_CV>,
                         cudaFuncAttributeMaxDynamicSharedMemorySize, DYNSMEM);
    cudaFuncSetAttribute(tgemm_k<EPI_RES>,
                         cudaFuncAttributeMaxDynamicSharedMemorySize, DYNSMEM);
    cudaFuncSetAttribute(tgemm_k<EPI_GELU>,
                         cudaFuncAttributeMaxDynamicSharedMemorySize, DYNSMEM);
    cudaFuncSetAttribute(tgemm_k<EPI_BIASRES>,
                         cudaFuncAttributeMaxDynamicSharedMemorySize, DYNSMEM);

    // 0) weight transposes (K-major) + fp16 conversion
    prep_w_k<<<256, 256>>>(g1_whg, g2_whg, g1_wout, g2_wout, p1_w, p2_w);
    // 1) LayerNorm 1 (fp16 out, feeds conv)
    ln_k<<<MTOT, 128>>>(x, norm_w, norm_b, hln);
    // 2) depthwise 3x3 conv (fp16 in/out, fp32 accum)
    dwconv_k<<<MTOT, DIM>>>(hln, dw_w, dw_b, hc);
    // 3) hg GEMMs with fused (c,v) epilogue (half2 cv out)
    dim3 gHG(HG2 / BROWS, MTOT / AROWS);
    tgemm_k<EPI_CV><<<gHG, 256, DYNSMEM>>>(hc, w1p, DIM, nullptr, nullptr, 0,
                                           HG2, nullptr, nullptr, cv1);
    tgemm_k<EPI_CV><<<gHG, 256, DYNSMEM>>>(hc, w2p, DIM, nullptr, nullptr, 0,
                                           HG2, nullptr, nullptr, cv2);
    // 4) chunked parallel scans (fwd + bwd in one grid per pass; fp16 h out)
    scan1_k<<<(2 * NBATCH * SNCH * DI) / 256, 256>>>();
    scan2_k<<<(2 * NBATCH * DI) / 256, 256>>>();
    scan3_k<<<(2 * NBATCH * SNCH * DI) / 256, 256>>>();
    // 5) x1 + x2 + residual (dual-K GEMM, fp32 out)
    dim3 gD(DIM / BROWS, MTOT / AROWS);
    tgemm_k<EPI_RES><<<gD, 256, DYNSMEM>>>(hs1, wo1t, DI, hs2, wo2t, DI,
                                           DIM, nullptr, x, hmid);
    // 6) LayerNorm 2 (fp16 out, feeds MLP GEMM)
    ln_k<<<MTOT, 128>>>(hmid, n2_w, n2_b, mn);
    // 7) MLP up + bias + GELU (fp16 out)
    tgemm_k<EPI_GELU><<<gHG, 256, DYNSMEM>>>(mn, p1t, DIM, nullptr, nullptr, 0,
                                             MLPD, p1_b, nullptr, m1);
    // 8) MLP down + bias + residual -> output (fp32 exact epilogue)
    tgemm_k<EPI_BIASRES><<<gD, 256, DYNSMEM>>>(m1, p2t, MLPD, nullptr, nullptr, 0,
                                               DIM, p2_b, hmid, out);
}

// round 13
// speedup vs baseline: 1.0101x; 1.0101x over previous
#include <cuda_runtime.h>
#include <cuda_fp16.h>
#include <math.h>
#include <stdint.h>

// ---------------- problem constants ----------------
#define NB_    56
#define L_     (NB_*NB_)       // 3136
#define NBATCH 16
#define DIM    384
#define DI     768
#define HG2    1536
#define MLPD   1536
#define MTOT   (NBATCH*L_)     // 50176

#define SCHUNK 64
#define SNCH   (L_/SCHUNK)     // 49

// ---------------- scratch ----------------
__device__ __half  g_hln [(size_t)MTOT*DIM];
__device__ __half  g_hc  [(size_t)MTOT*DIM];
__device__ __half2 g_cv1 [(size_t)MTOT*DI];    // (c,v) pairs per channel
__device__ __half2 g_cv2 [(size_t)MTOT*DI];
__device__ __half  g_hs1 [(size_t)MTOT*DI];
__device__ __half  g_hs2 [(size_t)MTOT*DI];
__device__ float   g_hmid[(size_t)MTOT*DIM];
__device__ __half  g_mn  [(size_t)MTOT*DIM];
__device__ __half  g_m1  [(size_t)MTOT*MLPD];
__device__ __half  g_w1p [HG2*DIM];   // [1536][384] K-major, (h,g) col-interleaved
__device__ __half  g_w2p [HG2*DIM];
__device__ __half  g_wo1t[DIM*DI];    // [384][768]
__device__ __half  g_wo2t[DIM*DI];
__device__ __half  g_p1t [MLPD*DIM];  // [1536][384]
__device__ __half  g_p2t [DIM*MLPD];  // [384][1536]
__device__ float2  g_sum[(size_t)2*NBATCH*DI*SNCH];  // chunk summaries / h_in

// ---------------- helpers ----------------
__device__ __forceinline__ uint32_t smem_u32(const void* p) {
    uint32_t a;
    asm("{ .reg .u64 t; cvta.to.shared.u64 t, %1; cvt.u32.u64 %0, t; }"
        : "=r"(a) : "l"(p));
    return a;
}
#define CP_ASYNC16(sa, gp) \
    asm volatile("cp.async.cg.shared.global [%0], [%1], 16;" :: "r"(sa), "l"(gp))

// f16-accumulate MMA: 2x the fp32-acc rate on the legacy HMMA pipe
__device__ __forceinline__ void mma_f16acc(uint32_t* d, const uint32_t* a,
                                           uint32_t b0, uint32_t b1) {
    asm volatile(
        "mma.sync.aligned.m16n8k16.row.col.f16.f16.f16.f16 "
        "{%0,%1}, {%2,%3,%4,%5}, {%6,%7}, {%0,%1};"
        : "+r"(d[0]), "+r"(d[1])
        : "r"(a[0]), "r"(a[1]), "r"(a[2]), "r"(a[3]), "r"(b0), "r"(b1));
}
__device__ __forceinline__ void ldsm_x4(uint32_t* r, uint32_t addr) {
    asm volatile("ldmatrix.sync.aligned.m8n8.x4.shared.b16 {%0,%1,%2,%3}, [%4];"
        : "=r"(r[0]), "=r"(r[1]), "=r"(r[2]), "=r"(r[3]) : "r"(addr));
}
// fast sigmoid(-x) = 1/(1+exp(x)) via MUFU.EX2 + MUFU.RCP (~2e-7 rel err)
__device__ __forceinline__ float fsign(float x) {
    return __fdividef(1.0f, 1.0f + __expf(x));
}

// ---------------- LayerNorm (fp32 in, fp16 out) ----------------
__global__ void ln_k(const float* __restrict__ x, const float* __restrict__ w,
                     const float* __restrict__ b, __half* __restrict__ o) {
    const int row = blockIdx.x;
    const int t = threadIdx.x;
    const float* xr = x + (size_t)row * DIM;
    float v0 = xr[t], v1 = xr[t + 128], v2 = xr[t + 256];
    float s = v0 + v1 + v2;
    float q = v0 * v0 + v1 * v1 + v2 * v2;
#pragma unroll
    for (int off = 16; off; off >>= 1) {
        s += __shfl_down_sync(0xffffffffu, s, off);
        q += __shfl_down_sync(0xffffffffu, q, off);
    }
    __shared__ float ss[4], qq[4];
    __shared__ float mu_s, rs_s;
    const int wid = t >> 5, ln = t & 31;
    if (ln == 0) { ss[wid] = s; qq[wid] = q; }
    __syncthreads();
    if (t == 0) {
        float S = ss[0] + ss[1] + ss[2] + ss[3];
        float Q = qq[0] + qq[1] + qq[2] + qq[3];
        float mu = S * (1.0f / DIM);
        float var = fmaxf(Q * (1.0f / DIM) - mu * mu, 0.0f);
        mu_s = mu;
        rs_s = rsqrtf(var + 1e-5f);
    }
    __syncthreads();
    const float mu = mu_s, rs = rs_s;
    __half* orow = o + (size_t)row * DIM;
    orow[t]       = __float2half_rn((v0 - mu) * rs * w[t]       + b[t]);
    orow[t + 128] = __float2half_rn((v1 - mu) * rs * w[t + 128] + b[t + 128]);
    orow[t + 256] = __float2half_rn((v2 - mu) * rs * w[t + 256] + b[t + 256]);
}

// ---------------- depthwise 3x3 conv (half in, half out, fp32 accum) ---------
__global__ void dwconv_k(const __half* __restrict__ x, const float* __restrict__ w,
                         const float* __restrict__ b, __half* __restrict__ o) {
    const int t = blockIdx.x;
    const int d = threadIdx.x;
    const int n = t / L_;
    const int l = t - n * L_;
    const int r = l / NB_, c = l - r * NB_;
    float acc = b[d];
    const float* wr = w + d * 9;
#pragma unroll
    for (int dr = -1; dr <= 1; ++dr) {
        const int rr = r + dr;
        if (rr < 0 || rr >= NB_) continue;
#pragma unroll
        for (int dc = -1; dc <= 1; ++dc) {
            const int cc = c + dc;
            if (cc < 0 || cc >= NB_) continue;
            acc += __half2float(x[((size_t)(n * L_ + rr * NB_ + cc)) * DIM + d]) *
                   wr[(dr + 1) * 3 + (dc + 1)];
        }
    }
    o[(size_t)t * DIM + d] = __float2half_rn(acc);
}

// ---------------- weight prep: transpose to K-major + half -------------------
__global__ void prep_w_k(const float* __restrict__ g1, const float* __restrict__ g2,
                         const float* __restrict__ wo1, const float* __restrict__ wo2,
                         const float* __restrict__ p1, const float* __restrict__ p2) {
    const int stride = gridDim.x * blockDim.x;
    const int i0 = blockIdx.x * blockDim.x + threadIdx.x;
    for (int i = i0; i < HG2 * DIM; i += stride) {
        const int j = i / DIM, k = i - j * DIM;
        const int src = k * HG2 + (j >> 1) + (j & 1) * DI;
        g_w1p[i] = __float2half_rn(g1[src]);
        g_w2p[i] = __float2half_rn(g2[src]);
    }
    for (int i = i0; i < DIM * DI; i += stride) {
        const int n = i / DI, k = i - n * DI;
        g_wo1t[i] = __float2half_rn(wo1[(size_t)k * DIM + n]);
        g_wo2t[i] = __float2half_rn(wo2[(size_t)k * DIM + n]);
    }
    for (int i = i0; i < MLPD * DIM; i += stride) {
        const int n = i / DIM, k = i - n * DIM;
        g_p1t[i] = __float2half_rn(p1[(size_t)k * MLPD + n]);
    }
    for (int i = i0; i < DIM * MLPD; i += stride) {
        const int n = i / MLPD, k = i - n * MLPD;
        g_p2t[i] = __float2half_rn(p2[(size_t)k * DIM + n]);
    }
}

// ---------------- chunked parallel minGRU scans (half2 cv) -------------------
__global__ void scan1_k() {
    const int gid = blockIdx.x * blockDim.x + threadIdx.x;
    const int ch = gid % DI;
    int r = gid / DI;
    const int j = r % SNCH; r /= SNCH;
    const int n = r % NBATCH;
    const int dir = r / NBATCH;
    const __half2* cv = dir ? g_cv2 : g_cv1;
    const size_t base = (size_t)n * L_ * DI + ch;
    int l = dir ? (L_ - 1 - j * SCHUNK) : j * SCHUNK;
    const int step = dir ? -1 : 1;
    float C = 1.0f, h = 0.0f;
#pragma unroll 4
    for (int i = 0; i < SCHUNK; ++i) {
        const float2 t = __half22float2(cv[base + (size_t)l * DI]);
        C *= t.x;
        h = fmaf(h, t.x, t.y);
        l += step;
    }
    g_sum[((size_t)((dir * NBATCH + n) * DI + ch)) * SNCH + j] = make_float2(C, h);
}

__global__ void scan2_k() {
    const int gid = blockIdx.x * blockDim.x + threadIdx.x;
    const int ch = gid % DI;
    int r = gid / DI;
    const int n = r % NBATCH;
    const int dir = r / NBATCH;
    float2* srow = g_sum + ((size_t)((dir * NBATCH + n) * DI + ch)) * SNCH;
    float h = 0.0f;
#pragma unroll 7
    for (int j = 0; j < SNCH; ++j) {
        const float2 s = srow[j];
        srow[j].x = h;                       // h_in for chunk j
        h = fmaf(h, s.x, s.y);
    }
}

__global__ void scan3_k() {
    const int gid = blockIdx.x * blockDim.x + threadIdx.x;
    const int ch = gid % DI;
    int r = gid / DI;
    const int j = r % SNCH; r /= SNCH;
    const int n = r % NBATCH;
    const int dir = r / NBATCH;
    const __half2* cv = dir ? g_cv2 : g_cv1;
    __half* hs = dir ? g_hs2 : g_hs1;
    const size_t base = (size_t)n * L_ * DI + ch;
    int l = dir ? (L_ - 1 - j * SCHUNK) : j * SCHUNK;
    const int step = dir ? -1 : 1;
    float h = g_sum[((size_t)((dir * NBATCH + n) * DI + ch)) * SNCH + j].x;
#pragma unroll 4
    for (int i = 0; i < SCHUNK; ++i) {
        const float2 t = __half22float2(cv[base + (size_t)l * DI]);
        h = fmaf(h, t.x, t.y);
        hs[base + (size_t)l * DI] = __float2half_rn(h);
        l += step;
    }
}

// -- f16 mma.sync GEMM: 128x128x64, f16 accumulate + per-k-tile fp32 fold -----
#define TS2     72                         // halfs per smem row (64 + 8 pad)
#define TILEH   (128 * TS2)                // halfs per operand tile
#define STAGE_B (2 * TILEH * 2)            // A+B bytes per stage = 36864
#define NSTG    3
#define DYNSMEM (NSTG * STAGE_B)           // 110592

#define EPI_CV      0
#define EPI_RES     1
#define EPI_GELU    2
#define EPI_BIASRES 3

template <int EPI>
__global__ void __launch_bounds__(256, 2)
tgemm_k(const __half* __restrict__ A1, const __half* __restrict__ B1, int K1,
        const __half* __restrict__ A2, const __half* __restrict__ B2, int K2,
        int N, const float* __restrict__ bias, const float* __restrict__ res,
        void* __restrict__ Cv) {
    extern __shared__ __half dynsmem[];
    const int tid = threadIdx.x;
    const int wid = tid >> 5, lane = tid & 31;
    const int g = lane >> 2, t = lane & 3;
    const int wm = (wid & 1) * 64, wn = (wid >> 1) * 32;
    const int bn = blockIdx.x, bm = blockIdx.y;
    const uint32_t sbase = smem_u32(dynsmem);

    // per-lane ldmatrix base offsets (bytes, within a stage)
    const int lj = lane >> 3, li = lane & 7;
    const uint32_t aoff =
        (uint32_t)(((wm + (lj & 1) * 8 + li) * TS2 + (lj >> 1) * 8) * 2);
    const uint32_t boff =
        (uint32_t)((TILEH + (wn + (lj & 1) * 8 + li) * TS2 + (lj >> 1) * 8) * 2);

    const int KT1 = K1 >> 6;
    const int KT = KT1 + (K2 >> 6);

    // hoisted per-thread global pointers (advance by 64 per k-tile)
    const int grow = tid >> 3;               // 0..31
    const int gcol = (tid & 7) * 8;          // fixed 8-half segment
    const __half* pA = A1 + (size_t)(bm * 128 + grow) * K1 + gcol;
    const __half* pB = B1 + (size_t)(bn * 128 + grow) * K1 + gcol;
    size_t str = (size_t)32 * K1;
    // smem per-thread store offsets (fixed)
    const uint32_t ssoff = (uint32_t)(grow * TS2 + gcol) * 2;

    float acc[4][4][4];
#pragma unroll
    for (int mt = 0; mt < 4; mt++)
#pragma unroll
        for (int nt = 0; nt < 4; nt++)
#pragma unroll
            for (int i = 0; i < 4; i++) acc[mt][nt][i] = 0.0f;

    int next_load = 0;
    // prologue: fully issue the first two stages (pipeline fill)
#pragma unroll
    for (int pl = 0; pl < 2; ++pl) {
        if (pl < KT) {
            if (next_load == KT1 && A2) {
                pA = A2 + (size_t)(bm * 128 + grow) * K2 + gcol;
                pB = B2 + (size_t)(bn * 128 + grow) * K2 + gcol;
                str = (size_t)32 * K2;
            }
            const uint32_t sa = sbase + (next_load % NSTG) * STAGE_B + ssoff;
#pragma unroll
            for (int i = 0; i < 4; ++i) {
                CP_ASYNC16(sa + i * (32 * TS2 * 2), pA + i * str);
                CP_ASYNC16(sa + TILEH * 2 + i * (32 * TS2 * 2), pB + i * str);
            }
            asm volatile("cp.async.commit_group;" ::: "memory");
            pA += 64; pB += 64;
            ++next_load;
        }
    }

    for (int kt = 0; kt < KT; ++kt) {
        if (kt + 1 < KT)
            asm volatile("cp.async.wait_group 1;" ::: "memory");
        else
            asm volatile("cp.async.wait_group 0;" ::: "memory");
        __syncthreads();

        // prefetch state for tile kt+2, interleaved into the MMA loop
        const bool pref = (next_load < KT);
        uint32_t spref = 0;
        if (pref) {
            if (next_load == KT1 && A2) {   // switch to second source
                pA = A2 + (size_t)(bm * 128 + grow) * K2 + gcol;
                pB = B2 + (size_t)(bn * 128 + grow) * K2 + gcol;
                str = (size_t)32 * K2;
            }
            spref = sbase + (next_load % NSTG) * STAGE_B + ssoff;
        }

        const uint32_t sa = sbase + (kt % NSTG) * STAGE_B;
        const uint32_t abase = sa + aoff;
        const uint32_t bbase = sa + boff;

        // fresh fp16 accumulators for this K=64 chunk
        uint32_t hacc[4][4][2];
#pragma unroll
        for (int mt = 0; mt < 4; ++mt)
#pragma unroll
            for (int nt = 0; nt < 4; ++nt) {
                hacc[mt][nt][0] = 0u;
                hacc[mt][nt][1] = 0u;
            }

#pragma unroll
        for (int ks = 0; ks < 4; ++ks) {
            const uint32_t ko = (uint32_t)(ks * 32);   // 16 halfs = 32 bytes
            uint32_t bf[2][4];
#pragma unroll
            for (int q = 0; q < 2; ++q)
                ldsm_x4(bf[q], bbase + q * (16 * TS2 * 2) + ko);
            if (pref) {   // 2 of 8 copies per ks, in the LDSM latency shadow
                CP_ASYNC16(spref + ks * (32 * TS2 * 2), pA + ks * str);
                CP_ASYNC16(spref + TILEH * 2 + ks * (32 * TS2 * 2),
                           pB + ks * str);
            }
#pragma unroll
            for (int mt = 0; mt < 4; ++mt) {
                uint32_t af[4];                 // single-buffered A fragment
                ldsm_x4(af, abase + mt * (16 * TS2 * 2) + ko);
#pragma unroll
                for (int nt = 0; nt < 4; ++nt)
                    mma_f16acc(hacc[mt][nt], af,
                               bf[nt >> 1][nt & 1], bf[nt >> 1][(nt & 1) + 2]);
            }
        }
        // fold the K=64 fp16 chunk into fp32 master accumulators
#pragma unroll
        for (int mt = 0; mt < 4; ++mt)
#pragma unroll
            for (int nt = 0; nt < 4; ++nt) {
                const float2 lo =
                    __half22float2(*(const __half2*)&hacc[mt][nt][0]);
                const float2 hi =
                    __half22float2(*(const __half2*)&hacc[mt][nt][1]);
                acc[mt][nt][0] += lo.x;
                acc[mt][nt][1] += lo.y;
                acc[mt][nt][2] += hi.x;
                acc[mt][nt][3] += hi.y;
            }
        if (pref) {
            asm volatile("cp.async.commit_group;" ::: "memory");
            pA += 64; pB += 64;
            ++next_load;
        }
    }

    // ---------------- fused epilogue (fast-math, direct paired stores) -------
#pragma unroll
    for (int mt = 0; mt < 4; ++mt) {
#pragma unroll
        for (int nt = 0; nt < 4; ++nt) {
            const int col = bn * 128 + wn + nt * 8 + 2 * t;
            const int r0 = bm * 128 + wm + mt * 16 + g;
#pragma unroll
            for (int h = 0; h < 2; ++h) {
                const int row = r0 + h * 8;
                const float v0 = acc[mt][nt][2 * h + 0];
                const float v1 = acc[mt][nt][2 * h + 1];
                const size_t idx = (size_t)row * N + col;
                if (EPI == EPI_CV) {
                    // (v0, v1) = (hidden, gate); c = sigmoid(-gate),
                    // tilde_h = h+0.5 (h>=0) else sigmoid(h); v = (1-c)*tilde_h
                    __half2* C = (__half2*)Cv;
                    const float cc = fsign(v1);          // sigmoid(-v1)
                    const float zz = 1.0f - cc;
                    const float sp = fsign(-v0);         // sigmoid(v0)
                    const float tld = (v0 >= 0.0f) ? (v0 + 0.5f) : sp;
                    C[idx >> 1] = __floats2half2_rn(cc, zz * tld);
                } else if (EPI == EPI_RES) {
                    float* C = (float*)Cv;
                    const float2 r = *(const float2*)&res[idx];
                    *(float2*)&C[idx] = make_float2(v0 + r.x, v1 + r.y);
                } else if (EPI == EPI_GELU) {
                    __half* C = (__half*)Cv;
                    const float2 b = *(const float2*)&bias[col];
                    const float t0 = v0 + b.x, t1 = v1 + b.y;
                    const float g0 = 0.5f * t0 * (1.0f + erff(t0 * 0.70710678f));
                    const float g1 = 0.5f * t1 * (1.0f + erff(t1 * 0.70710678f));
                    *(__half2*)&C[idx] = __floats2half2_rn(g0, g1);
                } else { // EPI_BIASRES
                    float* C = (float*)Cv;
                    const float2 r = *(const float2*)&res[idx];
                    const float2 b = *(const float2*)&bias[col];
                    *(float2*)&C[idx] = make_float2(v0 + b.x + r.x, v1 + b.y + r.y);
                }
            }
        }
    }
}

// ---------------- launch sequence ----------------
extern "C" void kernel_launch(void* const* d_in, const int* in_sizes, int n_in,
                              void* d_out, int out_size) {
    const float* x       = (const float*)d_in[0];
    const float* norm_w  = (const float*)d_in[1];
    const float* norm_b  = (const float*)d_in[2];
    const float* dw_w    = (const float*)d_in[3];
    const float* dw_b    = (const float*)d_in[4];
    const float* g1_whg  = (const float*)d_in[5];
    const float* g1_wout = (const float*)d_in[6];
    const float* g2_whg  = (const float*)d_in[7];
    const float* g2_wout = (const float*)d_in[8];
    const float* n2_w    = (const float*)d_in[9];
    const float* n2_b    = (const float*)d_in[10];
    const float* p1_w    = (const float*)d_in[11];
    const float* p1_b    = (const float*)d_in[12];
    const float* p2_w    = (const float*)d_in[13];
    const float* p2_b    = (const float*)d_in[14];
    float* out = (float*)d_out;

    float *hmid;
    __half2 *cv1, *cv2;
    __half *hln, *hc, *hs1, *hs2, *mn, *m1, *w1p, *w2p, *wo1t, *wo2t, *p1t, *p2t;
    cudaGetSymbolAddress((void**)&hln,  g_hln);
    cudaGetSymbolAddress((void**)&hc,   g_hc);
    cudaGetSymbolAddress((void**)&cv1,  g_cv1);
    cudaGetSymbolAddress((void**)&cv2,  g_cv2);
    cudaGetSymbolAddress((void**)&hs1,  g_hs1);
    cudaGetSymbolAddress((void**)&hs2,  g_hs2);
    cudaGetSymbolAddress((void**)&hmid, g_hmid);
    cudaGetSymbolAddress((void**)&mn,   g_mn);
    cudaGetSymbolAddress((void**)&m1,   g_m1);
    cudaGetSymbolAddress((void**)&w1p,  g_w1p);
    cudaGetSymbolAddress((void**)&w2p,  g_w2p);
    cudaGetSymbolAddress((void**)&wo1t, g_wo1t);
    cudaGetSymbolAddress((void**)&wo2t, g_wo2t);
    cudaGetSymbolAddress((void**)&p1t,  g_p1t);
    cudaGetSymbolAddress((void**)&p2t,  g_p2t);

    cudaFuncSetAttribute(tgemm_k<EPI_CV>,
                         cudaFuncAttributeMaxDynamicSharedMemorySize, DYNSMEM);
    cudaFuncSetAttribute(tgemm_k<EPI_RES>,
                         cudaFuncAttributeMaxDynamicSharedMemorySize, DYNSMEM);
    cudaFuncSetAttribute(tgemm_k<EPI_GELU>,
                         cudaFuncAttributeMaxDynamicSharedMemorySize, DYNSMEM);
    cudaFuncSetAttribute(tgemm_k<EPI_BIASRES>,
                         cudaFuncAttributeMaxDynamicSharedMemorySize, DYNSMEM);

    // 0) weight transposes (K-major) + fp16 conversion
    prep_w_k<<<256, 256>>>(g1_whg, g2_whg, g1_wout, g2_wout, p1_w, p2_w);
    // 1) LayerNorm 1 (fp16 out, feeds conv)
    ln_k<<<MTOT, 128>>>(x, norm_w, norm_b, hln);
    // 2) depthwise 3x3 conv (fp16 in/out, fp32 accum)
    dwconv_k<<<MTOT, DIM>>>(hln, dw_w, dw_b, hc);
    // 3) hg GEMMs with fused (c,v) epilogue (half2 cv out)
    dim3 gHG(HG2 / 128, MTOT / 128);
    tgemm_k<EPI_CV><<<gHG, 256, DYNSMEM>>>(hc, w1p, DIM, nullptr, nullptr, 0,
                                           HG2, nullptr, nullptr, cv1);
    tgemm_k<EPI_CV><<<gHG, 256, DYNSMEM>>>(hc, w2p, DIM, nullptr, nullptr, 0,
                                           HG2, nullptr, nullptr, cv2);
    // 4) chunked parallel scans (fwd + bwd in one grid per pass; fp16 h out)
    scan1_k<<<(2 * NBATCH * SNCH * DI) / 256, 256>>>();
    scan2_k<<<(2 * NBATCH * DI) / 256, 256>>>();
    scan3_k<<<(2 * NBATCH * SNCH * DI) / 256, 256>>>();
    // 5) x1 + x2 + residual (dual-K GEMM, fp32 out)
    dim3 gD(DIM / 128, MTOT / 128);
    tgemm_k<EPI_RES><<<gD, 256, DYNSMEM>>>(hs1, wo1t, DI, hs2, wo2t, DI,
                                           DIM, nullptr, x, hmid);
    // 6) LayerNorm 2 (fp16 out, feeds MLP GEMM)
    ln_k<<<MTOT, 128>>>(hmid, n2_w, n2_b, mn);
    // 7) MLP up + bias + GELU (fp16 out)
    tgemm_k<EPI_GELU><<<gHG, 256, DYNSMEM>>>(mn, p1t, DIM, nullptr, nullptr, 0,
                                             MLPD, p1_b, nullptr, m1);
    // 8) MLP down + bias + residual -> output (fp32 exact epilogue)
    tgemm_k<EPI_BIASRES><<<gD, 256, DYNSMEM>>>(m1, p2t, MLPD, nullptr, nullptr, 0,
                                               DIM, p2_b, hmid, out);
}

// round 14
// speedup vs baseline: 1.0714x; 1.0607x over previous
#include <cuda_runtime.h>
#include <cuda_fp16.h>
#include <math.h>
#include <stdint.h>

// ---------------- problem constants ----------------
#define NB_    56
#define L_     (NB_*NB_)       // 3136
#define NBATCH 16
#define DIM    384
#define DI     768
#define HG2    1536
#define MLPD   1536
#define MTOT   (NBATCH*L_)     // 50176

#define SCHUNK 64
#define SNCH   (L_/SCHUNK)     // 49

// ---------------- scratch ----------------
__device__ __half  g_hln [(size_t)MTOT*DIM];
__device__ __half  g_hc  [(size_t)MTOT*DIM];
__device__ __half2 g_cv1 [(size_t)MTOT*DI];    // (c,v) pairs per channel
__device__ __half2 g_cv2 [(size_t)MTOT*DI];
__device__ __half  g_hs1 [(size_t)MTOT*DI];
__device__ __half  g_hs2 [(size_t)MTOT*DI];
__device__ float   g_hmid[(size_t)MTOT*DIM];
__device__ __half  g_mn  [(size_t)MTOT*DIM];
__device__ __half  g_m1  [(size_t)MTOT*MLPD];
__device__ __half  g_w1p [HG2*DIM];   // [1536][384] K-major, (h,g) col-interleaved
__device__ __half  g_w2p [HG2*DIM];
__device__ __half  g_wo1t[DIM*DI];    // [384][768]
__device__ __half  g_wo2t[DIM*DI];
__device__ __half  g_p1t [MLPD*DIM];  // [1536][384]
__device__ __half  g_p2t [DIM*MLPD];  // [384][1536]
__device__ float2  g_sum[(size_t)2*NBATCH*DI*SNCH];  // chunk summaries / h_in

// ---------------- helpers ----------------
__device__ __forceinline__ uint32_t smem_u32(const void* p) {
    uint32_t a;
    asm("{ .reg .u64 t; cvta.to.shared.u64 t, %1; cvt.u32.u64 %0, t; }"
        : "=r"(a) : "l"(p));
    return a;
}
#define CP_ASYNC16(sa, gp) \
    asm volatile("cp.async.cg.shared.global [%0], [%1], 16;" :: "r"(sa), "l"(gp))

__device__ __forceinline__ void mma_f16(float* d, const uint32_t* a,
                                        uint32_t b0, uint32_t b1) {
    asm volatile(
        "mma.sync.aligned.m16n8k16.row.col.f32.f16.f16.f32 "
        "{%0,%1,%2,%3}, {%4,%5,%6,%7}, {%8,%9}, {%0,%1,%2,%3};"
        : "+f"(d[0]), "+f"(d[1]), "+f"(d[2]), "+f"(d[3])
        : "r"(a[0]), "r"(a[1]), "r"(a[2]), "r"(a[3]), "r"(b0), "r"(b1));
}
__device__ __forceinline__ void ldsm_x4(uint32_t* r, uint32_t addr) {
    asm volatile("ldmatrix.sync.aligned.m8n8.x4.shared.b16 {%0,%1,%2,%3}, [%4];"
        : "=r"(r[0]), "=r"(r[1]), "=r"(r[2]), "=r"(r[3]) : "r"(addr));
}

// ---------------- LayerNorm (fp32 in, fp16 out) ----------------
__global__ void ln_k(const float* __restrict__ x, const float* __restrict__ w,
                     const float* __restrict__ b, __half* __restrict__ o) {
    const int row = blockIdx.x;
    const int t = threadIdx.x;
    const float* xr = x + (size_t)row * DIM;
    float v0 = xr[t], v1 = xr[t + 128], v2 = xr[t + 256];
    float s = v0 + v1 + v2;
    float q = v0 * v0 + v1 * v1 + v2 * v2;
#pragma unroll
    for (int off = 16; off; off >>= 1) {
        s += __shfl_down_sync(0xffffffffu, s, off);
        q += __shfl_down_sync(0xffffffffu, q, off);
    }
    __shared__ float ss[4], qq[4];
    __shared__ float mu_s, rs_s;
    const int wid = t >> 5, ln = t & 31;
    if (ln == 0) { ss[wid] = s; qq[wid] = q; }
    __syncthreads();
    if (t == 0) {
        float S = ss[0] + ss[1] + ss[2] + ss[3];
        float Q = qq[0] + qq[1] + qq[2] + qq[3];
        float mu = S * (1.0f / DIM);
        float var = fmaxf(Q * (1.0f / DIM) - mu * mu, 0.0f);
        mu_s = mu;
        rs_s = rsqrtf(var + 1e-5f);
    }
    __syncthreads();
    const float mu = mu_s, rs = rs_s;
    __half* orow = o + (size_t)row * DIM;
    orow[t]       = __float2half_rn((v0 - mu) * rs * w[t]       + b[t]);
    orow[t + 128] = __float2half_rn((v1 - mu) * rs * w[t + 128] + b[t + 128]);
    orow[t + 256] = __float2half_rn((v2 - mu) * rs * w[t + 256] + b[t + 256]);
}

// ---------------- depthwise 3x3 conv (half in, half out, fp32 accum) ---------
__global__ void dwconv_k(const __half* __restrict__ x, const float* __restrict__ w,
                         const float* __restrict__ b, __half* __restrict__ o) {
    const int t = blockIdx.x;
    const int d = threadIdx.x;
    const int n = t / L_;
    const int l = t - n * L_;
    const int r = l / NB_, c = l - r * NB_;
    float acc = b[d];
    const float* wr = w + d * 9;
#pragma unroll
    for (int dr = -1; dr <= 1; ++dr) {
        const int rr = r + dr;
        if (rr < 0 || rr >= NB_) continue;
#pragma unroll
        for (int dc = -1; dc <= 1; ++dc) {
            const int cc = c + dc;
            if (cc < 0 || cc >= NB_) continue;
            acc += __half2float(x[((size_t)(n * L_ + rr * NB_ + cc)) * DIM + d]) *
                   wr[(dr + 1) * 3 + (dc + 1)];
        }
    }
    o[(size_t)t * DIM + d] = __float2half_rn(acc);
}

// ---------------- weight prep: transpose to K-major + half -------------------
__global__ void prep_w_k(const float* __restrict__ g1, const float* __restrict__ g2,
                         const float* __restrict__ wo1, const float* __restrict__ wo2,
                         const float* __restrict__ p1, const float* __restrict__ p2) {
    const int stride = gridDim.x * blockDim.x;
    const int i0 = blockIdx.x * blockDim.x + threadIdx.x;
    for (int i = i0; i < HG2 * DIM; i += stride) {
        const int j = i / DIM, k = i - j * DIM;
        const int src = k * HG2 + (j >> 1) + (j & 1) * DI;
        g_w1p[i] = __float2half_rn(g1[src]);
        g_w2p[i] = __float2half_rn(g2[src]);
    }
    for (int i = i0; i < DIM * DI; i += stride) {
        const int n = i / DI, k = i - n * DI;
        g_wo1t[i] = __float2half_rn(wo1[(size_t)k * DIM + n]);
        g_wo2t[i] = __float2half_rn(wo2[(size_t)k * DIM + n]);
    }
    for (int i = i0; i < MLPD * DIM; i += stride) {
        const int n = i / DIM, k = i - n * DIM;
        g_p1t[i] = __float2half_rn(p1[(size_t)k * MLPD + n]);
    }
    for (int i = i0; i < DIM * MLPD; i += stride) {
        const int n = i / MLPD, k = i - n * MLPD;
        g_p2t[i] = __float2half_rn(p2[(size_t)k * DIM + n]);
    }
}

// ---------------- chunked parallel minGRU scans (half2 cv) -------------------
__global__ void scan1_k() {
    const int gid = blockIdx.x * blockDim.x + threadIdx.x;
    const int ch = gid % DI;
    int r = gid / DI;
    const int j = r % SNCH; r /= SNCH;
    const int n = r % NBATCH;
    const int dir = r / NBATCH;
    const __half2* cv = dir ? g_cv2 : g_cv1;
    const size_t base = (size_t)n * L_ * DI + ch;
    int l = dir ? (L_ - 1 - j * SCHUNK) : j * SCHUNK;
    const int step = dir ? -1 : 1;
    float C = 1.0f, h = 0.0f;
#pragma unroll 4
    for (int i = 0; i < SCHUNK; ++i) {
        const float2 t = __half22float2(cv[base + (size_t)l * DI]);
        C *= t.x;
        h = fmaf(h, t.x, t.y);
        l += step;
    }
    g_sum[((size_t)((dir * NBATCH + n) * DI + ch)) * SNCH + j] = make_float2(C, h);
}

__global__ void scan2_k() {
    const int gid = blockIdx.x * blockDim.x + threadIdx.x;
    const int ch = gid % DI;
    int r = gid / DI;
    const int n = r % NBATCH;
    const int dir = r / NBATCH;
    float2* srow = g_sum + ((size_t)((dir * NBATCH + n) * DI + ch)) * SNCH;
    float h = 0.0f;
#pragma unroll 7
    for (int j = 0; j < SNCH; ++j) {
        const float2 s = srow[j];
        srow[j].x = h;                       // h_in for chunk j
        h = fmaf(h, s.x, s.y);
    }
}

__global__ void scan3_k() {
    const int gid = blockIdx.x * blockDim.x + threadIdx.x;
    const int ch = gid % DI;
    int r = gid / DI;
    const int j = r % SNCH; r /= SNCH;
    const int n = r % NBATCH;
    const int dir = r / NBATCH;
    const __half2* cv = dir ? g_cv2 : g_cv1;
    __half* hs = dir ? g_hs2 : g_hs1;
    const size_t base = (size_t)n * L_ * DI + ch;
    int l = dir ? (L_ - 1 - j * SCHUNK) : j * SCHUNK;
    const int step = dir ? -1 : 1;
    float h = g_sum[((size_t)((dir * NBATCH + n) * DI + ch)) * SNCH + j].x;
#pragma unroll 4
    for (int i = 0; i < SCHUNK; ++i) {
        const float2 t = __half22float2(cv[base + (size_t)l * DI]);
        h = fmaf(h, t.x, t.y);
        hs[base + (size_t)l * DI] = __float2half_rn(h);
        l += step;
    }
}

// ---------------- f16 mma.sync GEMM: 128x128x64, 3-stage, ldmatrix -----------
#define TS2     72                         // halfs per smem row (64 + 8 pad)
#define TILEH   (128 * TS2)                // halfs per operand tile
#define STAGE_B (2 * TILEH * 2)            // A+B bytes per stage = 36864
#define NSTG    3
#define DYNSMEM (NSTG * STAGE_B)           // 110592

#define EPI_CV      0
#define EPI_RES     1
#define EPI_GELU    2
#define EPI_BIASRES 3

template <int EPI>
__global__ void __launch_bounds__(256, 2)
tgemm_k(const __half* __restrict__ A1, const __half* __restrict__ B1, int K1,
        const __half* __restrict__ A2, const __half* __restrict__ B2, int K2,
        int N, const float* __restrict__ bias, const float* __restrict__ res,
        void* __restrict__ Cv) {
    extern __shared__ __half dynsmem[];
    const int tid = threadIdx.x;
    const int wid = tid >> 5, lane = tid & 31;
    const int g = lane >> 2, t = lane & 3;
    const int wm = (wid & 1) * 64, wn = (wid >> 1) * 32;
    const int bn = blockIdx.x, bm = blockIdx.y;
    const uint32_t sbase = smem_u32(dynsmem);

    // per-lane ldmatrix base offsets (bytes, within a stage)
    const int lj = lane >> 3, li = lane & 7;
    const uint32_t aoff =
        (uint32_t)(((wm + (lj & 1) * 8 + li) * TS2 + (lj >> 1) * 8) * 2);
    const uint32_t boff =
        (uint32_t)((TILEH + (wn + (lj & 1) * 8 + li) * TS2 + (lj >> 1) * 8) * 2);

    const int KT1 = K1 >> 6;
    const int KT = KT1 + (K2 >> 6);

    // hoisted per-thread global pointers (advance by 64 per k-tile)
    const int grow = tid >> 3;               // 0..31
    const int gcol = (tid & 7) * 8;          // fixed 8-half segment
    const __half* pA = A1 + (size_t)(bm * 128 + grow) * K1 + gcol;
    const __half* pB = B1 + (size_t)(bn * 128 + grow) * K1 + gcol;
    size_t str = (size_t)32 * K1;
    // smem per-thread store offsets (fixed)
    const uint32_t ssoff = (uint32_t)(grow * TS2 + gcol) * 2;

    float acc[4][4][4];
#pragma unroll
    for (int mt = 0; mt < 4; mt++)
#pragma unroll
        for (int nt = 0; nt < 4; nt++)
#pragma unroll
            for (int i = 0; i < 4; i++) acc[mt][nt][i] = 0.0f;

    int next_load = 0;
    // prologue: fully issue the first two stages (pipeline fill)
#pragma unroll
    for (int pl = 0; pl < 2; ++pl) {
        if (pl < KT) {
            if (next_load == KT1 && A2) {
                pA = A2 + (size_t)(bm * 128 + grow) * K2 + gcol;
                pB = B2 + (size_t)(bn * 128 + grow) * K2 + gcol;
                str = (size_t)32 * K2;
            }
            const uint32_t sa = sbase + (next_load % NSTG) * STAGE_B + ssoff;
#pragma unroll
            for (int i = 0; i < 4; ++i) {
                CP_ASYNC16(sa + i * (32 * TS2 * 2), pA + i * str);
                CP_ASYNC16(sa + TILEH * 2 + i * (32 * TS2 * 2), pB + i * str);
            }
            asm volatile("cp.async.commit_group;" ::: "memory");
            pA += 64; pB += 64;
            ++next_load;
        }
    }

    for (int kt = 0; kt < KT; ++kt) {
        if (kt + 1 < KT)
            asm volatile("cp.async.wait_group 1;" ::: "memory");
        else
            asm volatile("cp.async.wait_group 0;" ::: "memory");
        __syncthreads();

        // prefetch state for tile kt+2, interleaved into the MMA loop
        const bool pref = (next_load < KT);
        uint32_t spref = 0;
        if (pref) {
            if (next_load == KT1 && A2) {   // switch to second source
                pA = A2 + (size_t)(bm * 128 + grow) * K2 + gcol;
                pB = B2 + (size_t)(bn * 128 + grow) * K2 + gcol;
                str = (size_t)32 * K2;
            }
            spref = sbase + (next_load % NSTG) * STAGE_B + ssoff;
        }

        const uint32_t sa = sbase + (kt % NSTG) * STAGE_B;
        const uint32_t abase = sa + aoff;
        const uint32_t bbase = sa + boff;
#pragma unroll
        for (int ks = 0; ks < 4; ++ks) {
            const uint32_t ko = (uint32_t)(ks * 32);   // 16 halfs = 32 bytes
            uint32_t af[4][4], bf[2][4];
#pragma unroll
            for (int mt = 0; mt < 4; ++mt)
                ldsm_x4(af[mt], abase + mt * (16 * TS2 * 2) + ko);
#pragma unroll
            for (int q = 0; q < 2; ++q)
                ldsm_x4(bf[q], bbase + q * (16 * TS2 * 2) + ko);
            if (pref) {   // 2 of 8 copies per ks, in the LDSM latency shadow
                CP_ASYNC16(spref + ks * (32 * TS2 * 2), pA + ks * str);
                CP_ASYNC16(spref + TILEH * 2 + ks * (32 * TS2 * 2),
                           pB + ks * str);
            }
#pragma unroll
            for (int mt = 0; mt < 4; ++mt)
#pragma unroll
                for (int nt = 0; nt < 4; ++nt)
                    mma_f16(acc[mt][nt], af[mt],
                            bf[nt >> 1][nt & 1], bf[nt >> 1][(nt & 1) + 2]);
        }
        if (pref) {
            asm volatile("cp.async.commit_group;" ::: "memory");
            pA += 64; pB += 64;
            ++next_load;
        }
    }

    // ---------------- fused epilogue (fast-math, direct paired stores) -------
#pragma unroll
    for (int mt = 0; mt < 4; ++mt) {
#pragma unroll
        for (int nt = 0; nt < 4; ++nt) {
            const int col = bn * 128 + wn + nt * 8 + 2 * t;
            const int r0 = bm * 128 + wm + mt * 16 + g;
#pragma unroll
            for (int h = 0; h < 2; ++h) {
                const int row = r0 + h * 8;
                const float v0 = acc[mt][nt][2 * h + 0];
                const float v1 = acc[mt][nt][2 * h + 1];
                const size_t idx = (size_t)row * N + col;
                if (EPI == EPI_CV) {
                    // (v0, v1) = (hidden, gate)
                    // cc = sigmoid(-gate);  v = sigmoid(gate) * tilde_h
                    // tilde_h = v0+0.5 (v0>=0) else sigmoid(v0)
                    // 3 MUFU via shared reciprocal of (1+E1)*d2:
                    __half2* C = (__half2*)Cv;
                    const float E1 = __expf(v1);             // e^{gate}
                    const float E2 = __expf(fminf(v0, 0.0f)); // e^{min(v0,0)}
                    const bool pos = (v0 >= 0.0f);
                    const float d2  = pos ? 1.0f : (1.0f + E2);
                    const float num = pos ? (v0 + 0.5f) : E2;
                    const float R = __fdividef(1.0f, (1.0f + E1) * d2);
                    const float cc = R * d2;                 // sigmoid(-gate)
                    const float vv = E1 * R * num;           // sigmoid(g)*tld
                    C[idx >> 1] = __floats2half2_rn(cc, vv);
                } else if (EPI == EPI_RES) {
                    float* C = (float*)Cv;
                    const float2 r = *(const float2*)&res[idx];
                    *(float2*)&C[idx] = make_float2(v0 + r.x, v1 + r.y);
                } else if (EPI == EPI_GELU) {
                    __half* C = (__half*)Cv;
                    const float2 b = *(const float2*)&bias[col];
                    const float t0 = v0 + b.x, t1 = v1 + b.y;
                    const float g0 = 0.5f * t0 * (1.0f + erff(t0 * 0.70710678f));
                    const float g1 = 0.5f * t1 * (1.0f + erff(t1 * 0.70710678f));
                    *(__half2*)&C[idx] = __floats2half2_rn(g0, g1);
                } else { // EPI_BIASRES
                    float* C = (float*)Cv;
                    const float2 r = *(const float2*)&res[idx];
                    const float2 b = *(const float2*)&bias[col];
                    *(float2*)&C[idx] = make_float2(v0 + b.x + r.x, v1 + b.y + r.y);
                }
            }
        }
    }
}

// ---------------- launch sequence ----------------
extern "C" void kernel_launch(void* const* d_in, const int* in_sizes, int n_in,
                              void* d_out, int out_size) {
    const float* x       = (const float*)d_in[0];
    const float* norm_w  = (const float*)d_in[1];
    const float* norm_b  = (const float*)d_in[2];
    const float* dw_w    = (const float*)d_in[3];
    const float* dw_b    = (const float*)d_in[4];
    const float* g1_whg  = (const float*)d_in[5];
    const float* g1_wout = (const float*)d_in[6];
    const float* g2_whg  = (const float*)d_in[7];
    const float* g2_wout = (const float*)d_in[8];
    const float* n2_w    = (const float*)d_in[9];
    const float* n2_b    = (const float*)d_in[10];
    const float* p1_w    = (const float*)d_in[11];
    const float* p1_b    = (const float*)d_in[12];
    const float* p2_w    = (const float*)d_in[13];
    const float* p2_b    = (const float*)d_in[14];
    float* out = (float*)d_out;

    float *hmid;
    __half2 *cv1, *cv2;
    __half *hln, *hc, *hs1, *hs2, *mn, *m1, *w1p, *w2p, *wo1t, *wo2t, *p1t, *p2t;
    cudaGetSymbolAddress((void**)&hln,  g_hln);
    cudaGetSymbolAddress((void**)&hc,   g_hc);
    cudaGetSymbolAddress((void**)&cv1,  g_cv1);
    cudaGetSymbolAddress((void**)&cv2,  g_cv2);
    cudaGetSymbolAddress((void**)&hs1,  g_hs1);
    cudaGetSymbolAddress((void**)&hs2,  g_hs2);
    cudaGetSymbolAddress((void**)&hmid, g_hmid);
    cudaGetSymbolAddress((void**)&mn,   g_mn);
    cudaGetSymbolAddress((void**)&m1,   g_m1);
    cudaGetSymbolAddress((void**)&w1p,  g_w1p);
    cudaGetSymbolAddress((void**)&w2p,  g_w2p);
    cudaGetSymbolAddress((void**)&wo1t, g_wo1t);
    cudaGetSymbolAddress((void**)&wo2t, g_wo2t);
    cudaGetSymbolAddress((void**)&p1t,  g_p1t);
    cudaGetSymbolAddress((void**)&p2t,  g_p2t);

    cudaFuncSetAttribute(tgemm_k<EPI_CV>,
                         cudaFuncAttributeMaxDynamicSharedMemorySize, DYNSMEM);
    cudaFuncSetAttribute(tgemm_k<EPI_RES>,
                         cudaFuncAttributeMaxDynamicSharedMemorySize, DYNSMEM);
    cudaFuncSetAttribute(tgemm_k<EPI_GELU>,
                         cudaFuncAttributeMaxDynamicSharedMemorySize, DYNSMEM);
    cudaFuncSetAttribute(tgemm_k<EPI_BIASRES>,
                         cudaFuncAttributeMaxDynamicSharedMemorySize, DYNSMEM);

    // 0) weight transposes (K-major) + fp16 conversion
    prep_w_k<<<256, 256>>>(g1_whg, g2_whg, g1_wout, g2_wout, p1_w, p2_w);
    // 1) LayerNorm 1 (fp16 out, feeds conv)
    ln_k<<<MTOT, 128>>>(x, norm_w, norm_b, hln);
    // 2) depthwise 3x3 conv (fp16 in/out, fp32 accum)
    dwconv_k<<<MTOT, DIM>>>(hln, dw_w, dw_b, hc);
    // 3) hg GEMMs with fused (c,v) epilogue (half2 cv out)
    dim3 gHG(HG2 / 128, MTOT / 128);
    tgemm_k<EPI_CV><<<gHG, 256, DYNSMEM>>>(hc, w1p, DIM, nullptr, nullptr, 0,
                                           HG2, nullptr, nullptr, cv1);
    tgemm_k<EPI_CV><<<gHG, 256, DYNSMEM>>>(hc, w2p, DIM, nullptr, nullptr, 0,
                                           HG2, nullptr, nullptr, cv2);
    // 4) chunked parallel scans (fwd + bwd in one grid per pass; fp16 h out)
    scan1_k<<<(2 * NBATCH * SNCH * DI) / 256, 256>>>();
    scan2_k<<<(2 * NBATCH * DI) / 256, 256>>>();
    scan3_k<<<(2 * NBATCH * SNCH * DI) / 256, 256>>>();
    // 5) x1 + x2 + residual (dual-K GEMM, fp32 out)
    dim3 gD(DIM / 128, MTOT / 128);
    tgemm_k<EPI_RES><<<gD, 256, DYNSMEM>>>(hs1, wo1t, DI, hs2, wo2t, DI,
                                           DIM, nullptr, x, hmid);
    // 6) LayerNorm 2 (fp16 out, feeds MLP GEMM)
    ln_k<<<MTOT, 128>>>(hmid, n2_w, n2_b, mn);
    // 7) MLP up + bias + GELU (fp16 out)
    tgemm_k<EPI_GELU><<<gHG, 256, DYNSMEM>>>(mn, p1t, DIM, nullptr, nullptr, 0,
                                             MLPD, p1_b, nullptr, m1);
    // 8) MLP down + bias + residual -> output (fp32 exact epilogue)
    tgemm_k<EPI_BIASRES><<<gD, 256, DYNSMEM>>>(m1, p2t, MLPD, nullptr, nullptr, 0,
                                               DIM, p2_b, hmid, out);
}

// round 15
// speedup vs baseline: 1.1403x; 1.0643x over previous
#include <cuda_runtime.h>
#include <cuda_fp16.h>
#include <math.h>
#include <stdint.h>

// ---------------- problem constants ----------------
#define NB_    56
#define L_     (NB_*NB_)       // 3136
#define NBATCH 16
#define DIM    384
#define DI     768
#define HG2    1536
#define MLPD   1536
#define MTOT   (NBATCH*L_)     // 50176

#define SCHUNK 64
#define SNCH   (L_/SCHUNK)     // 49
#define NDN    (2*NBATCH)      // 32 (dir,batch) rows

// ---------------- scratch ----------------
__device__ __half  g_hln [(size_t)MTOT*DIM];
__device__ __half  g_hc  [(size_t)MTOT*DIM];
__device__ __half2 g_cv1 [(size_t)MTOT*DI];    // (c,v) pairs per channel
__device__ __half2 g_cv2 [(size_t)MTOT*DI];
__device__ __half  g_hs1 [(size_t)MTOT*DI];
__device__ __half  g_hs2 [(size_t)MTOT*DI];
__device__ float   g_hmid[(size_t)MTOT*DIM];
__device__ __half  g_mn  [(size_t)MTOT*DIM];
__device__ __half  g_m1  [(size_t)MTOT*MLPD];
__device__ __half  g_w1p [HG2*DIM];   // [1536][384] K-major, (h,g) col-interleaved
__device__ __half  g_w2p [HG2*DIM];
__device__ __half  g_wo1t[DIM*DI];    // [384][768]
__device__ __half  g_wo2t[DIM*DI];
__device__ __half  g_p1t [MLPD*DIM];  // [1536][384]
__device__ __half  g_p2t [DIM*MLPD];  // [384][1536]
// chunk summaries / h_in, J-MAJOR: [(j*NDN + dn)*DI + ch]
__device__ float2  g_sum[(size_t)SNCH*NDN*DI];

// ---------------- helpers ----------------
__device__ __forceinline__ uint32_t smem_u32(const void* p) {
    uint32_t a;
    asm("{ .reg .u64 t; cvta.to.shared.u64 t, %1; cvt.u32.u64 %0, t; }"
        : "=r"(a) : "l"(p));
    return a;
}
#define CP_ASYNC16(sa, gp) \
    asm volatile("cp.async.cg.shared.global [%0], [%1], 16;" :: "r"(sa), "l"(gp))

__device__ __forceinline__ void mma_f16(float* d, const uint32_t* a,
                                        uint32_t b0, uint32_t b1) {
    asm volatile(
        "mma.sync.aligned.m16n8k16.row.col.f32.f16.f16.f32 "
        "{%0,%1,%2,%3}, {%4,%5,%6,%7}, {%8,%9}, {%0,%1,%2,%3};"
        : "+f"(d[0]), "+f"(d[1]), "+f"(d[2]), "+f"(d[3])
        : "r"(a[0]), "r"(a[1]), "r"(a[2]), "r"(a[3]), "r"(b0), "r"(b1));
}
__device__ __forceinline__ void ldsm_x4(uint32_t* r, uint32_t addr) {
    asm volatile("ldmatrix.sync.aligned.m8n8.x4.shared.b16 {%0,%1,%2,%3}, [%4];"
        : "=r"(r[0]), "=r"(r[1]), "=r"(r[2]), "=r"(r[3]) : "r"(addr));
}

// ---------------- LayerNorm (fp32 in, fp16 out) ----------------
__global__ void ln_k(const float* __restrict__ x, const float* __restrict__ w,
                     const float* __restrict__ b, __half* __restrict__ o) {
    const int row = blockIdx.x;
    const int t = threadIdx.x;
    const float* xr = x + (size_t)row * DIM;
    float v0 = xr[t], v1 = xr[t + 128], v2 = xr[t + 256];
    float s = v0 + v1 + v2;
    float q = v0 * v0 + v1 * v1 + v2 * v2;
#pragma unroll
    for (int off = 16; off; off >>= 1) {
        s += __shfl_down_sync(0xffffffffu, s, off);
        q += __shfl_down_sync(0xffffffffu, q, off);
    }
    __shared__ float ss[4], qq[4];
    __shared__ float mu_s, rs_s;
    const int wid = t >> 5, ln = t & 31;
    if (ln == 0) { ss[wid] = s; qq[wid] = q; }
    __syncthreads();
    if (t == 0) {
        float S = ss[0] + ss[1] + ss[2] + ss[3];
        float Q = qq[0] + qq[1] + qq[2] + qq[3];
        float mu = S * (1.0f / DIM);
        float var = fmaxf(Q * (1.0f / DIM) - mu * mu, 0.0f);
        mu_s = mu;
        rs_s = rsqrtf(var + 1e-5f);
    }
    __syncthreads();
    const float mu = mu_s, rs = rs_s;
    __half* orow = o + (size_t)row * DIM;
    orow[t]       = __float2half_rn((v0 - mu) * rs * w[t]       + b[t]);
    orow[t + 128] = __float2half_rn((v1 - mu) * rs * w[t + 128] + b[t + 128]);
    orow[t + 256] = __float2half_rn((v2 - mu) * rs * w[t + 256] + b[t + 256]);
}

// ---------------- depthwise 3x3 conv (half in, half out, fp32 accum) ---------
__global__ void dwconv_k(const __half* __restrict__ x, const float* __restrict__ w,
                         const float* __restrict__ b, __half* __restrict__ o) {
    const int t = blockIdx.x;
    const int d = threadIdx.x;
    const int n = t / L_;
    const int l = t - n * L_;
    const int r = l / NB_, c = l - r * NB_;
    float acc = b[d];
    const float* wr = w + d * 9;
#pragma unroll
    for (int dr = -1; dr <= 1; ++dr) {
        const int rr = r + dr;
        if (rr < 0 || rr >= NB_) continue;
#pragma unroll
        for (int dc = -1; dc <= 1; ++dc) {
            const int cc = c + dc;
            if (cc < 0 || cc >= NB_) continue;
            acc += __half2float(x[((size_t)(n * L_ + rr * NB_ + cc)) * DIM + d]) *
                   wr[(dr + 1) * 3 + (dc + 1)];
        }
    }
    o[(size_t)t * DIM + d] = __float2half_rn(acc);
}

// ---------------- weight prep: transpose to K-major + half -------------------
__global__ void prep_w_k(const float* __restrict__ g1, const float* __restrict__ g2,
                         const float* __restrict__ wo1, const float* __restrict__ wo2,
                         const float* __restrict__ p1, const float* __restrict__ p2) {
    const int stride = gridDim.x * blockDim.x;
    const int i0 = blockIdx.x * blockDim.x + threadIdx.x;
    for (int i = i0; i < HG2 * DIM; i += stride) {
        const int j = i / DIM, k = i - j * DIM;
        const int src = k * HG2 + (j >> 1) + (j & 1) * DI;
        g_w1p[i] = __float2half_rn(g1[src]);
        g_w2p[i] = __float2half_rn(g2[src]);
    }
    for (int i = i0; i < DIM * DI; i += stride) {
        const int n = i / DI, k = i - n * DI;
        g_wo1t[i] = __float2half_rn(wo1[(size_t)k * DIM + n]);
        g_wo2t[i] = __float2half_rn(wo2[(size_t)k * DIM + n]);
    }
    for (int i = i0; i < MLPD * DIM; i += stride) {
        const int n = i / DIM, k = i - n * DIM;
        g_p1t[i] = __float2half_rn(p1[(size_t)k * MLPD + n]);
    }
    for (int i = i0; i < DIM * MLPD; i += stride) {
        const int n = i / MLPD, k = i - n * MLPD;
        g_p2t[i] = __float2half_rn(p2[(size_t)k * DIM + n]);
    }
}

// ------------- chunked parallel minGRU scans, 2 channels/thread --------------
// g_sum layout is j-major: g_sum[(j*NDN + dn)*DI + ch] -> scan2 coalesced.
__global__ void scan1_k() {
    const int gid = blockIdx.x * blockDim.x + threadIdx.x;  // NDN*SNCH*DI/2
    const int ch2 = gid % (DI / 2);
    int r = gid / (DI / 2);
    const int j = r % SNCH; r /= SNCH;
    const int dn = r;                        // dir*NBATCH + n
    const int dir = dn >> 4, n = dn & 15;
    const int ch = ch2 * 2;
    const __half2* cv = dir ? g_cv2 : g_cv1;
    const size_t base = (size_t)n * L_ * DI + ch;
    int l = dir ? (L_ - 1 - j * SCHUNK) : j * SCHUNK;
    const int step = dir ? -1 : 1;
    float C0 = 1.0f, h0 = 0.0f, C1 = 1.0f, h1 = 0.0f;
#pragma unroll 4
    for (int i = 0; i < SCHUNK; ++i) {
        const __half2* p = cv + base + (size_t)l * DI;
        const float2 t0 = __half22float2(p[0]);
        const float2 t1 = __half22float2(p[1]);
        C0 *= t0.x;  h0 = fmaf(h0, t0.x, t0.y);
        C1 *= t1.x;  h1 = fmaf(h1, t1.x, t1.y);
        l += step;
    }
    float4* out = (float4*)&g_sum[((size_t)j * NDN + dn) * DI + ch];
    *out = make_float4(C0, h0, C1, h1);
}

__global__ void scan2_k() {
    const int gid = blockIdx.x * blockDim.x + threadIdx.x;  // NDN*DI
    const int ch = gid % DI;
    const int dn = gid / DI;
    float h = 0.0f;
#pragma unroll 7
    for (int j = 0; j < SNCH; ++j) {
        float2* p = &g_sum[((size_t)j * NDN + dn) * DI + ch];
        const float2 s = *p;
        p->x = h;                            // h_in for chunk j
        h = fmaf(h, s.x, s.y);
    }
}

__global__ void scan3_k() {
    const int gid = blockIdx.x * blockDim.x + threadIdx.x;
    const int ch2 = gid % (DI / 2);
    int r = gid / (DI / 2);
    const int j = r % SNCH; r /= SNCH;
    const int dn = r;
    const int dir = dn >> 4, n = dn & 15;
    const int ch = ch2 * 2;
    const __half2* cv = dir ? g_cv2 : g_cv1;
    __half* hs = dir ? g_hs2 : g_hs1;
    const size_t base = (size_t)n * L_ * DI + ch;
    int l = dir ? (L_ - 1 - j * SCHUNK) : j * SCHUNK;
    const int step = dir ? -1 : 1;
    const float4 hin = *(const float4*)&g_sum[((size_t)j * NDN + dn) * DI + ch];
    float h0 = hin.x, h1 = hin.z;
#pragma unroll 4
    for (int i = 0; i < SCHUNK; ++i) {
        const __half2* p = cv + base + (size_t)l * DI;
        const float2 t0 = __half22float2(p[0]);
        const float2 t1 = __half22float2(p[1]);
        h0 = fmaf(h0, t0.x, t0.y);
        h1 = fmaf(h1, t1.x, t1.y);
        *(__half2*)&hs[base + (size_t)l * DI] = __floats2half2_rn(h0, h1);
        l += step;
    }
}

// ---------------- f16 mma.sync GEMM: 128x128x64, 3-stage, ldmatrix -----------
#define TS2     72                         // halfs per smem row (64 + 8 pad)
#define TILEH   (128 * TS2)                // halfs per operand tile
#define STAGE_B (2 * TILEH * 2)            // A+B bytes per stage = 36864
#define NSTG    3
#define DYNSMEM (NSTG * STAGE_B)           // 110592

#define EPI_CV      0
#define EPI_RES     1
#define EPI_GELU    2
#define EPI_BIASRES 3

template <int EPI>
__global__ void __launch_bounds__(256, 2)
tgemm_k(const __half* __restrict__ A1, const __half* __restrict__ B1, int K1,
        const __half* __restrict__ A2, const __half* __restrict__ B2, int K2,
        int N, const float* __restrict__ bias, const float* __restrict__ res,
        void* __restrict__ Cv) {
    extern __shared__ __half dynsmem[];
    const int tid = threadIdx.x;
    const int wid = tid >> 5, lane = tid & 31;
    const int g = lane >> 2, t = lane & 3;
    const int wm = (wid & 1) * 64, wn = (wid >> 1) * 32;
    const int bn = blockIdx.x, bm = blockIdx.y;
    const uint32_t sbase = smem_u32(dynsmem);

    // per-lane ldmatrix base offsets (bytes, within a stage)
    const int lj = lane >> 3, li = lane & 7;
    const uint32_t aoff =
        (uint32_t)(((wm + (lj & 1) * 8 + li) * TS2 + (lj >> 1) * 8) * 2);
    const uint32_t boff =
        (uint32_t)((TILEH + (wn + (lj & 1) * 8 + li) * TS2 + (lj >> 1) * 8) * 2);

    const int KT1 = K1 >> 6;
    const int KT = KT1 + (K2 >> 6);

    // hoisted per-thread global pointers (advance by 64 per k-tile)
    const int grow = tid >> 3;               // 0..31
    const int gcol = (tid & 7) * 8;          // fixed 8-half segment
    const __half* pA = A1 + (size_t)(bm * 128 + grow) * K1 + gcol;
    const __half* pB = B1 + (size_t)(bn * 128 + grow) * K1 + gcol;
    size_t str = (size_t)32 * K1;
    // smem per-thread store offsets (fixed)
    const uint32_t ssoff = (uint32_t)(grow * TS2 + gcol) * 2;

    float acc[4][4][4];
#pragma unroll
    for (int mt = 0; mt < 4; mt++)
#pragma unroll
        for (int nt = 0; nt < 4; nt++)
#pragma unroll
            for (int i = 0; i < 4; i++) acc[mt][nt][i] = 0.0f;

    int next_load = 0;
    // prologue: fully issue the first two stages (pipeline fill)
#pragma unroll
    for (int pl = 0; pl < 2; ++pl) {
        if (pl < KT) {
            if (next_load == KT1 && A2) {
                pA = A2 + (size_t)(bm * 128 + grow) * K2 + gcol;
                pB = B2 + (size_t)(bn * 128 + grow) * K2 + gcol;
                str = (size_t)32 * K2;
            }
            const uint32_t sa = sbase + (next_load % NSTG) * STAGE_B + ssoff;
#pragma unroll
            for (int i = 0; i < 4; ++i) {
                CP_ASYNC16(sa + i * (32 * TS2 * 2), pA + i * str);
                CP_ASYNC16(sa + TILEH * 2 + i * (32 * TS2 * 2), pB + i * str);
            }
            asm volatile("cp.async.commit_group;" ::: "memory");
            pA += 64; pB += 64;
            ++next_load;
        }
    }

    for (int kt = 0; kt < KT; ++kt) {
        if (kt + 1 < KT)
            asm volatile("cp.async.wait_group 1;" ::: "memory");
        else
            asm volatile("cp.async.wait_group 0;" ::: "memory");
        __syncthreads();

        // prefetch state for tile kt+2, interleaved into the MMA loop
        const bool pref = (next_load < KT);
        uint32_t spref = 0;
        if (pref) {
            if (next_load == KT1 && A2) {   // switch to second source
                pA = A2 + (size_t)(bm * 128 + grow) * K2 + gcol;
                pB = B2 + (size_t)(bn * 128 + grow) * K2 + gcol;
                str = (size_t)32 * K2;
            }
            spref = sbase + (next_load % NSTG) * STAGE_B + ssoff;
        }

        const uint32_t sa = sbase + (kt % NSTG) * STAGE_B;
        const uint32_t abase = sa + aoff;
        const uint32_t bbase = sa + boff;
#pragma unroll
        for (int ks = 0; ks < 4; ++ks) {
            const uint32_t ko = (uint32_t)(ks * 32);   // 16 halfs = 32 bytes
            uint32_t af[4][4], bf[2][4];
#pragma unroll
            for (int mt = 0; mt < 4; ++mt)
                ldsm_x4(af[mt], abase + mt * (16 * TS2 * 2) + ko);
#pragma unroll
            for (int q = 0; q < 2; ++q)
                ldsm_x4(bf[q], bbase + q * (16 * TS2 * 2) + ko);
            if (pref) {   // 2 of 8 copies per ks, in the LDSM latency shadow
                CP_ASYNC16(spref + ks * (32 * TS2 * 2), pA + ks * str);
                CP_ASYNC16(spref + TILEH * 2 + ks * (32 * TS2 * 2),
                           pB + ks * str);
            }
#pragma unroll
            for (int mt = 0; mt < 4; ++mt)
#pragma unroll
                for (int nt = 0; nt < 4; ++nt)
                    mma_f16(acc[mt][nt], af[mt],
                            bf[nt >> 1][nt & 1], bf[nt >> 1][(nt & 1) + 2]);
        }
        if (pref) {
            asm volatile("cp.async.commit_group;" ::: "memory");
            pA += 64; pB += 64;
            ++next_load;
        }
    }

    // ---------------- fused epilogue (fast-math, direct paired stores) -------
#pragma unroll
    for (int mt = 0; mt < 4; ++mt) {
#pragma unroll
        for (int nt = 0; nt < 4; ++nt) {
            const int col = bn * 128 + wn + nt * 8 + 2 * t;
            const int r0 = bm * 128 + wm + mt * 16 + g;
#pragma unroll
            for (int h = 0; h < 2; ++h) {
                const int row = r0 + h * 8;
                const float v0 = acc[mt][nt][2 * h + 0];
                const float v1 = acc[mt][nt][2 * h + 1];
                const size_t idx = (size_t)row * N + col;
                if (EPI == EPI_CV) {
                    // (v0, v1) = (hidden, gate)
                    // cc = sigmoid(-gate);  v = sigmoid(gate) * tilde_h
                    // tilde_h = v0+0.5 (v0>=0) else sigmoid(v0)
                    // 3 MUFU via shared reciprocal of (1+E1)*d2:
                    __half2* C = (__half2*)Cv;
                    const float E1 = __expf(v1);             // e^{gate}
                    const float E2 = __expf(fminf(v0, 0.0f)); // e^{min(v0,0)}
                    const bool pos = (v0 >= 0.0f);
                    const float d2  = pos ? 1.0f : (1.0f + E2);
                    const float num = pos ? (v0 + 0.5f) : E2;
                    const float R = __fdividef(1.0f, (1.0f + E1) * d2);
                    const float cc = R * d2;                 // sigmoid(-gate)
                    const float vv = E1 * R * num;           // sigmoid(g)*tld
                    C[idx >> 1] = __floats2half2_rn(cc, vv);
                } else if (EPI == EPI_RES) {
                    float* C = (float*)Cv;
                    const float2 r = *(const float2*)&res[idx];
                    *(float2*)&C[idx] = make_float2(v0 + r.x, v1 + r.y);
                } else if (EPI == EPI_GELU) {
                    __half* C = (__half*)Cv;
                    const float2 b = *(const float2*)&bias[col];
                    const float t0 = v0 + b.x, t1 = v1 + b.y;
                    const float g0 = 0.5f * t0 * (1.0f + erff(t0 * 0.70710678f));
                    const float g1 = 0.5f * t1 * (1.0f + erff(t1 * 0.70710678f));
                    *(__half2*)&C[idx] = __floats2half2_rn(g0, g1);
                } else { // EPI_BIASRES
                    float* C = (float*)Cv;
                    const float2 r = *(const float2*)&res[idx];
                    const float2 b = *(const float2*)&bias[col];
                    *(float2*)&C[idx] = make_float2(v0 + b.x + r.x, v1 + b.y + r.y);
                }
            }
        }
    }
}

// ---------------- launch sequence ----------------
extern "C" void kernel_launch(void* const* d_in, const int* in_sizes, int n_in,
                              void* d_out, int out_size) {
    const float* x       = (const float*)d_in[0];
    const float* norm_w  = (const float*)d_in[1];
    const float* norm_b  = (const float*)d_in[2];
    const float* dw_w    = (const float*)d_in[3];
    const float* dw_b    = (const float*)d_in[4];
    const float* g1_whg  = (const float*)d_in[5];
    const float* g1_wout = (const float*)d_in[6];
    const float* g2_whg  = (const float*)d_in[7];
    const float* g2_wout = (const float*)d_in[8];
    const float* n2_w    = (const float*)d_in[9];
    const float* n2_b    = (const float*)d_in[10];
    const float* p1_w    = (const float*)d_in[11];
    const float* p1_b    = (const float*)d_in[12];
    const float* p2_w    = (const float*)d_in[13];
    const float* p2_b    = (const float*)d_in[14];
    float* out = (float*)d_out;

    float *hmid;
    __half2 *cv1, *cv2;
    __half *hln, *hc, *hs1, *hs2, *mn, *m1, *w1p, *w2p, *wo1t, *wo2t, *p1t, *p2t;
    cudaGetSymbolAddress((void**)&hln,  g_hln);
    cudaGetSymbolAddress((void**)&hc,   g_hc);
    cudaGetSymbolAddress((void**)&cv1,  g_cv1);
    cudaGetSymbolAddress((void**)&cv2,  g_cv2);
    cudaGetSymbolAddress((void**)&hs1,  g_hs1);
    cudaGetSymbolAddress((void**)&hs2,  g_hs2);
    cudaGetSymbolAddress((void**)&hmid, g_hmid);
    cudaGetSymbolAddress((void**)&mn,   g_mn);
    cudaGetSymbolAddress((void**)&m1,   g_m1);
    cudaGetSymbolAddress((void**)&w1p,  g_w1p);
    cudaGetSymbolAddress((void**)&w2p,  g_w2p);
    cudaGetSymbolAddress((void**)&wo1t, g_wo1t);
    cudaGetSymbolAddress((void**)&wo2t, g_wo2t);
    cudaGetSymbolAddress((void**)&p1t,  g_p1t);
    cudaGetSymbolAddress((void**)&p2t,  g_p2t);

    cudaFuncSetAttribute(tgemm_k<EPI_CV>,
                         cudaFuncAttributeMaxDynamicSharedMemorySize, DYNSMEM);
    cudaFuncSetAttribute(tgemm_k<EPI_RES>,
                         cudaFuncAttributeMaxDynamicSharedMemorySize, DYNSMEM);
    cudaFuncSetAttribute(tgemm_k<EPI_GELU>,
                         cudaFuncAttributeMaxDynamicSharedMemorySize, DYNSMEM);
    cudaFuncSetAttribute(tgemm_k<EPI_BIASRES>,
                         cudaFuncAttributeMaxDynamicSharedMemorySize, DYNSMEM);

    // 0) weight transposes (K-major) + fp16 conversion
    prep_w_k<<<256, 256>>>(g1_whg, g2_whg, g1_wout, g2_wout, p1_w, p2_w);
    // 1) LayerNorm 1 (fp16 out, feeds conv)
    ln_k<<<MTOT, 128>>>(x, norm_w, norm_b, hln);
    // 2) depthwise 3x3 conv (fp16 in/out, fp32 accum)
    dwconv_k<<<MTOT, DIM>>>(hln, dw_w, dw_b, hc);
    // 3) hg GEMMs with fused (c,v) epilogue (half2 cv out)
    dim3 gHG(HG2 / 128, MTOT / 128);
    tgemm_k<EPI_CV><<<gHG, 256, DYNSMEM>>>(hc, w1p, DIM, nullptr, nullptr, 0,
                                           HG2, nullptr, nullptr, cv1);
    tgemm_k<EPI_CV><<<gHG, 256, DYNSMEM>>>(hc, w2p, DIM, nullptr, nullptr, 0,
                                           HG2, nullptr, nullptr, cv2);
    // 4) chunked parallel scans, 2 channels/thread, j-major summaries
    scan1_k<<<(NDN * SNCH * DI / 2) / 256, 256>>>();
    scan2_k<<<(NDN * DI) / 256, 256>>>();
    scan3_k<<<(NDN * SNCH * DI / 2) / 256, 256>>>();
    // 5) x1 + x2 + residual (dual-K GEMM, fp32 out)
    dim3 gD(DIM / 128, MTOT / 128);
    tgemm_k<EPI_RES><<<gD, 256, DYNSMEM>>>(hs1, wo1t, DI, hs2, wo2t, DI,
                                           DIM, nullptr, x, hmid);
    // 6) LayerNorm 2 (fp16 out, feeds MLP GEMM)
    ln_k<<<MTOT, 128>>>(hmid, n2_w, n2_b, mn);
    // 7) MLP up + bias + GELU (fp16 out)
    tgemm_k<EPI_GELU><<<gHG, 256, DYNSMEM>>>(mn, p1t, DIM, nullptr, nullptr, 0,
                                             MLPD, p1_b, nullptr, m1);
    // 8) MLP down + bias + residual -> output (fp32 exact epilogue)
    tgemm_k<EPI_BIASRES><<<gD, 256, DYNSMEM>>>(m1, p2t, MLPD, nullptr, nullptr, 0,
                                               DIM, p2_b, hmid, out);
}

// round 16
// speedup vs baseline: 1.1759x; 1.0312x over previous
#include <cuda_runtime.h>
#include <cuda_fp16.h>
#include <math.h>
#include <stdint.h>

// ---------------- problem constants ----------------
#define NB_    56
#define L_     (NB_*NB_)       // 3136
#define NBATCH 16
#define DIM    384
#define DI     768
#define HG2    1536
#define MLPD   1536
#define MTOT   (NBATCH*L_)     // 50176

#define SCHUNK 64
#define SNCH   (L_/SCHUNK)     // 49
#define NDN    (2*NBATCH)      // 32 (dir,batch) rows

// ---------------- scratch ----------------
__device__ __half  g_hln [(size_t)MTOT*DIM];
__device__ __half  g_hc  [(size_t)MTOT*DIM];
__device__ __half2 g_cv1 [(size_t)MTOT*DI];    // (c,v) pairs per channel
__device__ __half2 g_cv2 [(size_t)MTOT*DI];
__device__ __half  g_hs1 [(size_t)MTOT*DI];
__device__ __half  g_hs2 [(size_t)MTOT*DI];
__device__ float   g_hmid[(size_t)MTOT*DIM];
__device__ __half  g_mn  [(size_t)MTOT*DIM];
__device__ __half  g_m1  [(size_t)MTOT*MLPD];
__device__ __half  g_w1p [HG2*DIM];   // [1536][384] K-major, (h,g) col-interleaved
__device__ __half  g_w2p [HG2*DIM];
__device__ __half  g_wo1t[DIM*DI];    // [384][768]
__device__ __half  g_wo2t[DIM*DI];
__device__ __half  g_p1t [MLPD*DIM];  // [1536][384]
__device__ __half  g_p2t [DIM*MLPD];  // [384][1536]
// chunk summaries / h_in, J-MAJOR: [(j*NDN + dn)*DI + ch]
__device__ float2  g_sum[(size_t)SNCH*NDN*DI];

// ---------------- helpers ----------------
__device__ __forceinline__ uint32_t smem_u32(const void* p) {
    uint32_t a;
    asm("{ .reg .u64 t; cvta.to.shared.u64 t, %1; cvt.u32.u64 %0, t; }"
        : "=r"(a) : "l"(p));
    return a;
}
#define CP_ASYNC16(sa, gp) \
    asm volatile("cp.async.cg.shared.global [%0], [%1], 16;" :: "r"(sa), "l"(gp))

__device__ __forceinline__ void mma_f16(float* d, const uint32_t* a,
                                        uint32_t b0, uint32_t b1) {
    asm volatile(
        "mma.sync.aligned.m16n8k16.row.col.f32.f16.f16.f32 "
        "{%0,%1,%2,%3}, {%4,%5,%6,%7}, {%8,%9}, {%0,%1,%2,%3};"
        : "+f"(d[0]), "+f"(d[1]), "+f"(d[2]), "+f"(d[3])
        : "r"(a[0]), "r"(a[1]), "r"(a[2]), "r"(a[3]), "r"(b0), "r"(b1));
}
__device__ __forceinline__ void ldsm_x4(uint32_t* r, uint32_t addr) {
    asm volatile("ldmatrix.sync.aligned.m8n8.x4.shared.b16 {%0,%1,%2,%3}, [%4];"
        : "=r"(r[0]), "=r"(r[1]), "=r"(r[2]), "=r"(r[3]) : "r"(addr));
}
// fast exact-enough GELU (tanh form, 2 MUFU): max |diff vs erf form| ~3e-4
__device__ __forceinline__ float fgelu(float x) {
    const float u = 0.7978845608f * fmaf(0.044715f * x * x, x, x);
    const float e = __expf(2.0f * fabsf(u));
    float th = 1.0f - __fdividef(2.0f, 1.0f + e);
    th = (u < 0.0f) ? -th : th;
    return 0.5f * x * (1.0f + th);
}

// ---------------- LayerNorm (fp32 in, fp16 out) ----------------
__global__ void ln_k(const float* __restrict__ x, const float* __restrict__ w,
                     const float* __restrict__ b, __half* __restrict__ o) {
    const int row = blockIdx.x;
    const int t = threadIdx.x;
    const float* xr = x + (size_t)row * DIM;
    float v0 = xr[t], v1 = xr[t + 128], v2 = xr[t + 256];
    float s = v0 + v1 + v2;
    float q = v0 * v0 + v1 * v1 + v2 * v2;
#pragma unroll
    for (int off = 16; off; off >>= 1) {
        s += __shfl_down_sync(0xffffffffu, s, off);
        q += __shfl_down_sync(0xffffffffu, q, off);
    }
    __shared__ float ss[4], qq[4];
    __shared__ float mu_s, rs_s;
    const int wid = t >> 5, ln = t & 31;
    if (ln == 0) { ss[wid] = s; qq[wid] = q; }
    __syncthreads();
    if (t == 0) {
        float S = ss[0] + ss[1] + ss[2] + ss[3];
        float Q = qq[0] + qq[1] + qq[2] + qq[3];
        float mu = S * (1.0f / DIM);
        float var = fmaxf(Q * (1.0f / DIM) - mu * mu, 0.0f);
        mu_s = mu;
        rs_s = rsqrtf(var + 1e-5f);
    }
    __syncthreads();
    const float mu = mu_s, rs = rs_s;
    __half* orow = o + (size_t)row * DIM;
    orow[t]       = __float2half_rn((v0 - mu) * rs * w[t]       + b[t]);
    orow[t + 128] = __float2half_rn((v1 - mu) * rs * w[t + 128] + b[t + 128]);
    orow[t + 256] = __float2half_rn((v2 - mu) * rs * w[t + 256] + b[t + 256]);
}

// ------- depthwise 3x3 conv: 2 channels/thread via half2, fp32 accum ---------
__global__ void dwconv_k(const __half2* __restrict__ x, const float* __restrict__ w,
                         const float* __restrict__ b, __half2* __restrict__ o) {
    const int t = blockIdx.x;
    const int d = threadIdx.x;            // 0..191 = channel pair
    const int n = t / L_;
    const int l = t - n * L_;
    const int r = l / NB_, c = l - r * NB_;
    float a0 = b[2 * d], a1 = b[2 * d + 1];
    const float* w0 = w + (2 * d) * 9;
    const float* w1 = w + (2 * d + 1) * 9;
#pragma unroll
    for (int dr = -1; dr <= 1; ++dr) {
        const int rr = r + dr;
        if (rr < 0 || rr >= NB_) continue;
#pragma unroll
        for (int dc = -1; dc <= 1; ++dc) {
            const int cc = c + dc;
            if (cc < 0 || cc >= NB_) continue;
            const float2 v = __half22float2(
                x[((size_t)(n * L_ + rr * NB_ + cc)) * (DIM / 2) + d]);
            const int tap = (dr + 1) * 3 + (dc + 1);
            a0 = fmaf(v.x, w0[tap], a0);
            a1 = fmaf(v.y, w1[tap], a1);
        }
    }
    o[(size_t)t * (DIM / 2) + d] = __floats2half2_rn(a0, a1);
}

// ---------------- weight prep: transpose to K-major + half -------------------
__global__ void prep_w_k(const float* __restrict__ g1, const float* __restrict__ g2,
                         const float* __restrict__ wo1, const float* __restrict__ wo2,
                         const float* __restrict__ p1, const float* __restrict__ p2) {
    const int stride = gridDim.x * blockDim.x;
    const int i0 = blockIdx.x * blockDim.x + threadIdx.x;
    for (int i = i0; i < HG2 * DIM; i += stride) {
        const int j = i / DIM, k = i - j * DIM;
        const int src = k * HG2 + (j >> 1) + (j & 1) * DI;
        g_w1p[i] = __float2half_rn(g1[src]);
        g_w2p[i] = __float2half_rn(g2[src]);
    }
    for (int i = i0; i < DIM * DI; i += stride) {
        const int n = i / DI, k = i - n * DI;
        g_wo1t[i] = __float2half_rn(wo1[(size_t)k * DIM + n]);
        g_wo2t[i] = __float2half_rn(wo2[(size_t)k * DIM + n]);
    }
    for (int i = i0; i < MLPD * DIM; i += stride) {
        const int n = i / DIM, k = i - n * DIM;
        g_p1t[i] = __float2half_rn(p1[(size_t)k * MLPD + n]);
    }
    for (int i = i0; i < DIM * MLPD; i += stride) {
        const int n = i / MLPD, k = i - n * MLPD;
        g_p2t[i] = __float2half_rn(p2[(size_t)k * DIM + n]);
    }
}

// ------------- chunked parallel minGRU scans, 4 channels/thread --------------
// g_sum layout is j-major: g_sum[(j*NDN + dn)*DI + ch] -> scan2 coalesced.
__global__ void scan1_k() {
    const int gid = blockIdx.x * blockDim.x + threadIdx.x;  // NDN*SNCH*DI/4
    const int ch4 = gid % (DI / 4);
    int r = gid / (DI / 4);
    const int j = r % SNCH; r /= SNCH;
    const int dn = r;                        // dir*NBATCH + n
    const int dir = dn >> 4, n = dn & 15;
    const int ch = ch4 * 4;
    const __half2* cv = dir ? g_cv2 : g_cv1;
    const size_t base = (size_t)n * L_ * DI + ch;
    int l = dir ? (L_ - 1 - j * SCHUNK) : j * SCHUNK;
    const int step = dir ? -1 : 1;
    float C0 = 1.f, h0 = 0.f, C1 = 1.f, h1 = 0.f;
    float C2 = 1.f, h2 = 0.f, C3 = 1.f, h3 = 0.f;
#pragma unroll 4
    for (int i = 0; i < SCHUNK; ++i) {
        const uint4 raw = *(const uint4*)(cv + base + (size_t)l * DI);
        const float2 t0 = __half22float2(*(const __half2*)&raw.x);
        const float2 t1 = __half22float2(*(const __half2*)&raw.y);
        const float2 t2 = __half22float2(*(const __half2*)&raw.z);
        const float2 t3 = __half22float2(*(const __half2*)&raw.w);
        C0 *= t0.x;  h0 = fmaf(h0, t0.x, t0.y);
        C1 *= t1.x;  h1 = fmaf(h1, t1.x, t1.y);
        C2 *= t2.x;  h2 = fmaf(h2, t2.x, t2.y);
        C3 *= t3.x;  h3 = fmaf(h3, t3.x, t3.y);
        l += step;
    }
    float4* out = (float4*)&g_sum[((size_t)j * NDN + dn) * DI + ch];
    out[0] = make_float4(C0, h0, C1, h1);
    out[1] = make_float4(C2, h2, C3, h3);
}

__global__ void scan2_k() {
    const int gid = blockIdx.x * blockDim.x + threadIdx.x;  // NDN*DI
    const int ch = gid % DI;
    const int dn = gid / DI;
    float h = 0.0f;
#pragma unroll 7
    for (int j = 0; j < SNCH; ++j) {
        float2* p = &g_sum[((size_t)j * NDN + dn) * DI + ch];
        const float2 s = *p;
        p->x = h;                            // h_in for chunk j
        h = fmaf(h, s.x, s.y);
    }
}

__global__ void scan3_k() {
    const int gid = blockIdx.x * blockDim.x + threadIdx.x;
    const int ch4 = gid % (DI / 4);
    int r = gid / (DI / 4);
    const int j = r % SNCH; r /= SNCH;
    const int dn = r;
    const int dir = dn >> 4, n = dn & 15;
    const int ch = ch4 * 4;
    const __half2* cv = dir ? g_cv2 : g_cv1;
    __half* hs = dir ? g_hs2 : g_hs1;
    const size_t base = (size_t)n * L_ * DI + ch;
    int l = dir ? (L_ - 1 - j * SCHUNK) : j * SCHUNK;
    const int step = dir ? -1 : 1;
    const float4* hin = (const float4*)&g_sum[((size_t)j * NDN + dn) * DI + ch];
    const float4 ha = hin[0], hb = hin[1];
    float h0 = ha.x, h1 = ha.z, h2 = hb.x, h3 = hb.z;
#pragma unroll 4
    for (int i = 0; i < SCHUNK; ++i) {
        const uint4 raw = *(const uint4*)(cv + base + (size_t)l * DI);
        const float2 t0 = __half22float2(*(const __half2*)&raw.x);
        const float2 t1 = __half22float2(*(const __half2*)&raw.y);
        const float2 t2 = __half22float2(*(const __half2*)&raw.z);
        const float2 t3 = __half22float2(*(const __half2*)&raw.w);
        h0 = fmaf(h0, t0.x, t0.y);
        h1 = fmaf(h1, t1.x, t1.y);
        h2 = fmaf(h2, t2.x, t2.y);
        h3 = fmaf(h3, t3.x, t3.y);
        uint2 st;
        *(__half2*)&st.x = __floats2half2_rn(h0, h1);
        *(__half2*)&st.y = __floats2half2_rn(h2, h3);
        *(uint2*)&hs[base + (size_t)l * DI] = st;
        l += step;
    }
}

// ---------------- f16 mma.sync GEMM: 128x128x64, 3-stage, ldmatrix -----------
#define TS2     72                         // halfs per smem row (64 + 8 pad)
#define TILEH   (128 * TS2)                // halfs per operand tile
#define STAGE_B (2 * TILEH * 2)            // A+B bytes per stage = 36864
#define NSTG    3
#define DYNSMEM (NSTG * STAGE_B)           // 110592

#define EPI_CV      0
#define EPI_RES     1
#define EPI_GELU    2
#define EPI_BIASRES 3

template <int EPI>
__global__ void __launch_bounds__(256, 2)
tgemm_k(const __half* __restrict__ A1, const __half* __restrict__ B1, int K1,
        const __half* __restrict__ A2, const __half* __restrict__ B2, int K2,
        int N, const float* __restrict__ bias, const float* __restrict__ res,
        void* __restrict__ Cv) {
    extern __shared__ __half dynsmem[];
    const int tid = threadIdx.x;
    const int wid = tid >> 5, lane = tid & 31;
    const int g = lane >> 2, t = lane & 3;
    const int wm = (wid & 1) * 64, wn = (wid >> 1) * 32;
    const int bn = blockIdx.x, bm = blockIdx.y;
    const uint32_t sbase = smem_u32(dynsmem);

    // per-lane ldmatrix base offsets (bytes, within a stage)
    const int lj = lane >> 3, li = lane & 7;
    const uint32_t aoff =
        (uint32_t)(((wm + (lj & 1) * 8 + li) * TS2 + (lj >> 1) * 8) * 2);
    const uint32_t boff =
        (uint32_t)((TILEH + (wn + (lj & 1) * 8 + li) * TS2 + (lj >> 1) * 8) * 2);

    const int KT1 = K1 >> 6;
    const int KT = KT1 + (K2 >> 6);

    // hoisted per-thread global pointers (advance by 64 per k-tile)
    const int grow = tid >> 3;               // 0..31
    const int gcol = (tid & 7) * 8;          // fixed 8-half segment
    const __half* pA = A1 + (size_t)(bm * 128 + grow) * K1 + gcol;
    const __half* pB = B1 + (size_t)(bn * 128 + grow) * K1 + gcol;
    size_t str = (size_t)32 * K1;
    // smem per-thread store offsets (fixed)
    const uint32_t ssoff = (uint32_t)(grow * TS2 + gcol) * 2;

    float acc[4][4][4];
#pragma unroll
    for (int mt = 0; mt < 4; mt++)
#pragma unroll
        for (int nt = 0; nt < 4; nt++)
#pragma unroll
            for (int i = 0; i < 4; i++) acc[mt][nt][i] = 0.0f;

    int next_load = 0;
    // prologue: fully issue the first two stages (pipeline fill)
#pragma unroll
    for (int pl = 0; pl < 2; ++pl) {
        if (pl < KT) {
            if (next_load == KT1 && A2) {
                pA = A2 + (size_t)(bm * 128 + grow) * K2 + gcol;
                pB = B2 + (size_t)(bn * 128 + grow) * K2 + gcol;
                str = (size_t)32 * K2;
            }
            const uint32_t sa = sbase + (next_load % NSTG) * STAGE_B + ssoff;
#pragma unroll
            for (int i = 0; i < 4; ++i) {
                CP_ASYNC16(sa + i * (32 * TS2 * 2), pA + i * str);
                CP_ASYNC16(sa + TILEH * 2 + i * (32 * TS2 * 2), pB + i * str);
            }
            asm volatile("cp.async.commit_group;" ::: "memory");
            pA += 64; pB += 64;
            ++next_load;
        }
    }

    for (int kt = 0; kt < KT; ++kt) {
        if (kt + 1 < KT)
            asm volatile("cp.async.wait_group 1;" ::: "memory");
        else
            asm volatile("cp.async.wait_group 0;" ::: "memory");
        __syncthreads();

        // prefetch state for tile kt+2, interleaved into the MMA loop
        const bool pref = (next_load < KT);
        uint32_t spref = 0;
        if (pref) {
            if (next_load == KT1 && A2) {   // switch to second source
                pA = A2 + (size_t)(bm * 128 + grow) * K2 + gcol;
                pB = B2 + (size_t)(bn * 128 + grow) * K2 + gcol;
                str = (size_t)32 * K2;
            }
            spref = sbase + (next_load % NSTG) * STAGE_B + ssoff;
        }

        const uint32_t sa = sbase + (kt % NSTG) * STAGE_B;
        const uint32_t abase = sa + aoff;
        const uint32_t bbase = sa + boff;
#pragma unroll
        for (int ks = 0; ks < 4; ++ks) {
            const uint32_t ko = (uint32_t)(ks * 32);   // 16 halfs = 32 bytes
            uint32_t af[4][4], bf[2][4];
#pragma unroll
            for (int mt = 0; mt < 4; ++mt)
                ldsm_x4(af[mt], abase + mt * (16 * TS2 * 2) + ko);
#pragma unroll
            for (int q = 0; q < 2; ++q)
                ldsm_x4(bf[q], bbase + q * (16 * TS2 * 2) + ko);
            if (pref) {   // 2 of 8 copies per ks, in the LDSM latency shadow
                CP_ASYNC16(spref + ks * (32 * TS2 * 2), pA + ks * str);
                CP_ASYNC16(spref + TILEH * 2 + ks * (32 * TS2 * 2),
                           pB + ks * str);
            }
#pragma unroll
            for (int mt = 0; mt < 4; ++mt)
#pragma unroll
                for (int nt = 0; nt < 4; ++nt)
                    mma_f16(acc[mt][nt], af[mt],
                            bf[nt >> 1][nt & 1], bf[nt >> 1][(nt & 1) + 2]);
        }
        if (pref) {
            asm volatile("cp.async.commit_group;" ::: "memory");
            pA += 64; pB += 64;
            ++next_load;
        }
    }

    // ---------------- fused epilogue (fast-math, direct paired stores) -------
#pragma unroll
    for (int mt = 0; mt < 4; ++mt) {
#pragma unroll
        for (int nt = 0; nt < 4; ++nt) {
            const int col = bn * 128 + wn + nt * 8 + 2 * t;
            const int r0 = bm * 128 + wm + mt * 16 + g;
#pragma unroll
            for (int h = 0; h < 2; ++h) {
                const int row = r0 + h * 8;
                const float v0 = acc[mt][nt][2 * h + 0];
                const float v1 = acc[mt][nt][2 * h + 1];
                const size_t idx = (size_t)row * N + col;
                if (EPI == EPI_CV) {
                    // (v0, v1) = (hidden, gate)
                    // cc = sigmoid(-gate);  v = sigmoid(gate) * tilde_h
                    // tilde_h = v0+0.5 (v0>=0) else sigmoid(v0)
                    // 3 MUFU via shared reciprocal of (1+E1)*d2:
                    __half2* C = (__half2*)Cv;
                    const float E1 = __expf(v1);             // e^{gate}
                    const float E2 = __expf(fminf(v0, 0.0f)); // e^{min(v0,0)}
                    const bool pos = (v0 >= 0.0f);
                    const float d2  = pos ? 1.0f : (1.0f + E2);
                    const float num = pos ? (v0 + 0.5f) : E2;
                    const float R = __fdividef(1.0f, (1.0f + E1) * d2);
                    const float cc = R * d2;                 // sigmoid(-gate)
                    const float vv = E1 * R * num;           // sigmoid(g)*tld
                    C[idx >> 1] = __floats2half2_rn(cc, vv);
                } else if (EPI == EPI_RES) {
                    float* C = (float*)Cv;
                    const float2 r = *(const float2*)&res[idx];
                    *(float2*)&C[idx] = make_float2(v0 + r.x, v1 + r.y);
                } else if (EPI == EPI_GELU) {
                    __half* C = (__half*)Cv;
                    const float2 b = *(const float2*)&bias[col];
                    *(__half2*)&C[idx] =
                        __floats2half2_rn(fgelu(v0 + b.x), fgelu(v1 + b.y));
                } else { // EPI_BIASRES
                    float* C = (float*)Cv;
                    const float2 r = *(const float2*)&res[idx];
                    const float2 b = *(const float2*)&bias[col];
                    *(float2*)&C[idx] = make_float2(v0 + b.x + r.x, v1 + b.y + r.y);
                }
            }
        }
    }
}

// ---------------- launch sequence ----------------
extern "C" void kernel_launch(void* const* d_in, const int* in_sizes, int n_in,
                              void* d_out, int out_size) {
    const float* x       = (const float*)d_in[0];
    const float* norm_w  = (const float*)d_in[1];
    const float* norm_b  = (const float*)d_in[2];
    const float* dw_w    = (const float*)d_in[3];
    const float* dw_b    = (const float*)d_in[4];
    const float* g1_whg  = (const float*)d_in[5];
    const float* g1_wout = (const float*)d_in[6];
    const float* g2_whg  = (const float*)d_in[7];
    const float* g2_wout = (const float*)d_in[8];
    const float* n2_w    = (const float*)d_in[9];
    const float* n2_b    = (const float*)d_in[10];
    const float* p1_w    = (const float*)d_in[11];
    const float* p1_b    = (const float*)d_in[12];
    const float* p2_w    = (const float*)d_in[13];
    const float* p2_b    = (const float*)d_in[14];
    float* out = (float*)d_out;

    float *hmid;
    __half2 *cv1, *cv2;
    __half *hln, *hc, *hs1, *hs2, *mn, *m1, *w1p, *w2p, *wo1t, *wo2t, *p1t, *p2t;
    cudaGetSymbolAddress((void**)&hln,  g_hln);
    cudaGetSymbolAddress((void**)&hc,   g_hc);
    cudaGetSymbolAddress((void**)&cv1,  g_cv1);
    cudaGetSymbolAddress((void**)&cv2,  g_cv2);
    cudaGetSymbolAddress((void**)&hs1,  g_hs1);
    cudaGetSymbolAddress((void**)&hs2,  g_hs2);
    cudaGetSymbolAddress((void**)&hmid, g_hmid);
    cudaGetSymbolAddress((void**)&mn,   g_mn);
    cudaGetSymbolAddress((void**)&m1,   g_m1);
    cudaGetSymbolAddress((void**)&w1p,  g_w1p);
    cudaGetSymbolAddress((void**)&w2p,  g_w2p);
    cudaGetSymbolAddress((void**)&wo1t, g_wo1t);
    cudaGetSymbolAddress((void**)&wo2t, g_wo2t);
    cudaGetSymbolAddress((void**)&p1t,  g_p1t);
    cudaGetSymbolAddress((void**)&p2t,  g_p2t);

    cudaFuncSetAttribute(tgemm_k<EPI_CV>,
                         cudaFuncAttributeMaxDynamicSharedMemorySize, DYNSMEM);
    cudaFuncSetAttribute(tgemm_k<EPI_RES>,
                         cudaFuncAttributeMaxDynamicSharedMemorySize, DYNSMEM);
    cudaFuncSetAttribute(tgemm_k<EPI_GELU>,
                         cudaFuncAttributeMaxDynamicSharedMemorySize, DYNSMEM);
    cudaFuncSetAttribute(tgemm_k<EPI_BIASRES>,
                         cudaFuncAttributeMaxDynamicSharedMemorySize, DYNSMEM);

    // 0) weight transposes (K-major) + fp16 conversion
    prep_w_k<<<256, 256>>>(g1_whg, g2_whg, g1_wout, g2_wout, p1_w, p2_w);
    // 1) LayerNorm 1 (fp16 out, feeds conv)
    ln_k<<<MTOT, 128>>>(x, norm_w, norm_b, hln);
    // 2) depthwise 3x3 conv (half2, 2 channels/thread, fp32 accum)
    dwconv_k<<<MTOT, DIM / 2>>>((const __half2*)hln, dw_w, dw_b, (__half2*)hc);
    // 3) hg GEMMs with fused (c,v) epilogue (half2 cv out)
    dim3 gHG(HG2 / 128, MTOT / 128);
    tgemm_k<EPI_CV><<<gHG, 256, DYNSMEM>>>(hc, w1p, DIM, nullptr, nullptr, 0,
                                           HG2, nullptr, nullptr, cv1);
    tgemm_k<EPI_CV><<<gHG, 256, DYNSMEM>>>(hc, w2p, DIM, nullptr, nullptr, 0,
                                           HG2, nullptr, nullptr, cv2);
    // 4) chunked parallel scans, 4 channels/thread, j-major summaries
    scan1_k<<<(NDN * SNCH * DI / 4) / 256, 256>>>();
    scan2_k<<<(NDN * DI) / 256, 256>>>();
    scan3_k<<<(NDN * SNCH * DI / 4) / 256, 256>>>();
    // 5) x1 + x2 + residual (dual-K GEMM, fp32 out)
    dim3 gD(DIM / 128, MTOT / 128);
    tgemm_k<EPI_RES><<<gD, 256, DYNSMEM>>>(hs1, wo1t, DI, hs2, wo2t, DI,
                                           DIM, nullptr, x, hmid);
    // 6) LayerNorm 2 (fp16 out, feeds MLP GEMM)
    ln_k<<<MTOT, 128>>>(hmid, n2_w, n2_b, mn);
    // 7) MLP up + bias + GELU (fp16 out)
    tgemm_k<EPI_GELU><<<gHG, 256, DYNSMEM>>>(mn, p1t, DIM, nullptr, nullptr, 0,
                                             MLPD, p1_b, nullptr, m1);
    // 8) MLP down + bias + residual -> output (fp32 exact epilogue)
    tgemm_k<EPI_BIASRES><<<gD, 256, DYNSMEM>>>(m1, p2t, MLPD, nullptr, nullptr, 0,
                                               DIM, p2_b, hmid, out);
}

// round 17
// speedup vs baseline: 1.2266x; 1.0431x over previous
#include <cuda_runtime.h>
#include <cuda_fp16.h>
#include <math.h>
#include <stdint.h>

// ---------------- problem constants ----------------
#define NB_    56
#define L_     (NB_*NB_)       // 3136
#define NBATCH 16
#define DIM    384
#define DI     768
#define HG2    1536
#define MLPD   1536
#define MTOT   (NBATCH*L_)     // 50176

#define SCHUNK 64
#define SNCH   (L_/SCHUNK)     // 49
#define NDN    (2*NBATCH)      // 32 (dir,batch) rows

// ---------------- scratch ----------------
__device__ __half  g_hln [(size_t)MTOT*DIM];
__device__ __half  g_hc  [(size_t)MTOT*DIM];
__device__ __half2 g_cv1 [(size_t)MTOT*DI];    // (c,v) pairs per channel
__device__ __half2 g_cv2 [(size_t)MTOT*DI];
__device__ __half  g_hs1 [(size_t)MTOT*DI];
__device__ __half  g_hs2 [(size_t)MTOT*DI];
__device__ float   g_hmid[(size_t)MTOT*DIM];
__device__ __half  g_mn  [(size_t)MTOT*DIM];
__device__ __half  g_m1  [(size_t)MTOT*MLPD];
__device__ __half  g_w1p [HG2*DIM];   // [1536][384] K-major, (h,g) col-interleaved
__device__ __half  g_w2p [HG2*DIM];
__device__ __half  g_wo1t[DIM*DI];    // [384][768]
__device__ __half  g_wo2t[DIM*DI];
__device__ __half  g_p1t [MLPD*DIM];  // [1536][384]
__device__ __half  g_p2t [DIM*MLPD];  // [384][1536]
// chunk summaries / h_in, J-MAJOR: [(j*NDN + dn)*DI + ch]
__device__ float2  g_sum[(size_t)SNCH*NDN*DI];

// ---------------- helpers ----------------
__device__ __forceinline__ uint32_t smem_u32(const void* p) {
    uint32_t a;
    asm("{ .reg .u64 t; cvta.to.shared.u64 t, %1; cvt.u32.u64 %0, t; }"
        : "=r"(a) : "l"(p));
    return a;
}
#define CP_ASYNC16(sa, gp) \
    asm volatile("cp.async.cg.shared.global [%0], [%1], 16;" :: "r"(sa), "l"(gp))

__device__ __forceinline__ void mma_f16(float* d, const uint32_t* a,
                                        uint32_t b0, uint32_t b1) {
    asm volatile(
        "mma.sync.aligned.m16n8k16.row.col.f32.f16.f16.f32 "
        "{%0,%1,%2,%3}, {%4,%5,%6,%7}, {%8,%9}, {%0,%1,%2,%3};"
        : "+f"(d[0]), "+f"(d[1]), "+f"(d[2]), "+f"(d[3])
        : "r"(a[0]), "r"(a[1]), "r"(a[2]), "r"(a[3]), "r"(b0), "r"(b1));
}
__device__ __forceinline__ void ldsm_x4(uint32_t* r, uint32_t addr) {
    asm volatile("ldmatrix.sync.aligned.m8n8.x4.shared.b16 {%0,%1,%2,%3}, [%4];"
        : "=r"(r[0]), "=r"(r[1]), "=r"(r[2]), "=r"(r[3]) : "r"(addr));
}
// single-MUFU tanh (sm_75+ baseline PTX)
__device__ __forceinline__ float ftanh(float x) {
    float r;
    asm("tanh.approx.f32 %0, %1;" : "=f"(r) : "f"(x));
    return r;
}
// fast GELU via 1 MUFU tanh per value
__device__ __forceinline__ float fgelu(float x) {
    const float u = 0.7978845608f * fmaf(0.044715f * x * x, x, x);
    return 0.5f * x * (1.0f + ftanh(u));
}

// ---------------- LayerNorm (fp32 in, fp16 out) ----------------
__global__ void ln_k(const float* __restrict__ x, const float* __restrict__ w,
                     const float* __restrict__ b, __half* __restrict__ o) {
    const int row = blockIdx.x;
    const int t = threadIdx.x;
    const float* xr = x + (size_t)row * DIM;
    float v0 = xr[t], v1 = xr[t + 128], v2 = xr[t + 256];
    float s = v0 + v1 + v2;
    float q = v0 * v0 + v1 * v1 + v2 * v2;
#pragma unroll
    for (int off = 16; off; off >>= 1) {
        s += __shfl_down_sync(0xffffffffu, s, off);
        q += __shfl_down_sync(0xffffffffu, q, off);
    }
    __shared__ float ss[4], qq[4];
    __shared__ float mu_s, rs_s;
    const int wid = t >> 5, ln = t & 31;
    if (ln == 0) { ss[wid] = s; qq[wid] = q; }
    __syncthreads();
    if (t == 0) {
        float S = ss[0] + ss[1] + ss[2] + ss[3];
        float Q = qq[0] + qq[1] + qq[2] + qq[3];
        float mu = S * (1.0f / DIM);
        float var = fmaxf(Q * (1.0f / DIM) - mu * mu, 0.0f);
        mu_s = mu;
        rs_s = rsqrtf(var + 1e-5f);
    }
    __syncthreads();
    const float mu = mu_s, rs = rs_s;
    __half* orow = o + (size_t)row * DIM;
    orow[t]       = __float2half_rn((v0 - mu) * rs * w[t]       + b[t]);
    orow[t + 128] = __float2half_rn((v1 - mu) * rs * w[t + 128] + b[t + 128]);
    orow[t + 256] = __float2half_rn((v2 - mu) * rs * w[t + 256] + b[t + 256]);
}

// ------- depthwise 3x3 conv: 2 channels/thread via half2, fp32 accum ---------
__global__ void dwconv_k(const __half2* __restrict__ x, const float* __restrict__ w,
                         const float* __restrict__ b, __half2* __restrict__ o) {
    const int t = blockIdx.x;
    const int d = threadIdx.x;            // 0..191 = channel pair
    const int n = t / L_;
    const int l = t - n * L_;
    const int r = l / NB_, c = l - r * NB_;
    float a0 = b[2 * d], a1 = b[2 * d + 1];
    const float* w0 = w + (2 * d) * 9;
    const float* w1 = w + (2 * d + 1) * 9;
#pragma unroll
    for (int dr = -1; dr <= 1; ++dr) {
        const int rr = r + dr;
        if (rr < 0 || rr >= NB_) continue;
#pragma unroll
        for (int dc = -1; dc <= 1; ++dc) {
            const int cc = c + dc;
            if (cc < 0 || cc >= NB_) continue;
            const float2 v = __half22float2(
                x[((size_t)(n * L_ + rr * NB_ + cc)) * (DIM / 2) + d]);
            const int tap = (dr + 1) * 3 + (dc + 1);
            a0 = fmaf(v.x, w0[tap], a0);
            a1 = fmaf(v.y, w1[tap], a1);
        }
    }
    o[(size_t)t * (DIM / 2) + d] = __floats2half2_rn(a0, a1);
}

// ---------------- weight prep: transpose to K-major + half -------------------
__global__ void prep_w_k(const float* __restrict__ g1, const float* __restrict__ g2,
                         const float* __restrict__ wo1, const float* __restrict__ wo2,
                         const float* __restrict__ p1, const float* __restrict__ p2) {
    const int stride = gridDim.x * blockDim.x;
    const int i0 = blockIdx.x * blockDim.x + threadIdx.x;
    for (int i = i0; i < HG2 * DIM; i += stride) {
        const int j = i / DIM, k = i - j * DIM;
        const int src = k * HG2 + (j >> 1) + (j & 1) * DI;
        g_w1p[i] = __float2half_rn(g1[src]);
        g_w2p[i] = __float2half_rn(g2[src]);
    }
    for (int i = i0; i < DIM * DI; i += stride) {
        const int n = i / DI, k = i - n * DI;
        g_wo1t[i] = __float2half_rn(wo1[(size_t)k * DIM + n]);
        g_wo2t[i] = __float2half_rn(wo2[(size_t)k * DIM + n]);
    }
    for (int i = i0; i < MLPD * DIM; i += stride) {
        const int n = i / DIM, k = i - n * DIM;
        g_p1t[i] = __float2half_rn(p1[(size_t)k * MLPD + n]);
    }
    for (int i = i0; i < DIM * MLPD; i += stride) {
        const int n = i / MLPD, k = i - n * MLPD;
        g_p2t[i] = __float2half_rn(p2[(size_t)k * DIM + n]);
    }
}

// ------------- chunked parallel minGRU scans, 4 channels/thread --------------
// g_sum layout is j-major: g_sum[(j*NDN + dn)*DI + ch] -> scan2 coalesced.
__global__ void scan1_k() {
    const int gid = blockIdx.x * blockDim.x + threadIdx.x;  // NDN*SNCH*DI/4
    const int ch4 = gid % (DI / 4);
    int r = gid / (DI / 4);
    const int j = r % SNCH; r /= SNCH;
    const int dn = r;                        // dir*NBATCH + n
    const int dir = dn >> 4, n = dn & 15;
    const int ch = ch4 * 4;
    const __half2* cv = dir ? g_cv2 : g_cv1;
    const size_t base = (size_t)n * L_ * DI + ch;
    int l = dir ? (L_ - 1 - j * SCHUNK) : j * SCHUNK;
    const int step = dir ? -1 : 1;
    float C0 = 1.f, h0 = 0.f, C1 = 1.f, h1 = 0.f;
    float C2 = 1.f, h2 = 0.f, C3 = 1.f, h3 = 0.f;
#pragma unroll 4
    for (int i = 0; i < SCHUNK; ++i) {
        const uint4 raw = *(const uint4*)(cv + base + (size_t)l * DI);
        const float2 t0 = __half22float2(*(const __half2*)&raw.x);
        const float2 t1 = __half22float2(*(const __half2*)&raw.y);
        const float2 t2 = __half22float2(*(const __half2*)&raw.z);
        const float2 t3 = __half22float2(*(const __half2*)&raw.w);
        C0 *= t0.x;  h0 = fmaf(h0, t0.x, t0.y);
        C1 *= t1.x;  h1 = fmaf(h1, t1.x, t1.y);
        C2 *= t2.x;  h2 = fmaf(h2, t2.x, t2.y);
        C3 *= t3.x;  h3 = fmaf(h3, t3.x, t3.y);
        l += step;
    }
    float4* out = (float4*)&g_sum[((size_t)j * NDN + dn) * DI + ch];
    out[0] = make_float4(C0, h0, C1, h1);
    out[1] = make_float4(C2, h2, C3, h3);
}

__global__ void scan2_k() {
    const int gid = blockIdx.x * blockDim.x + threadIdx.x;  // NDN*DI
    const int ch = gid % DI;
    const int dn = gid / DI;
    float h = 0.0f;
#pragma unroll 7
    for (int j = 0; j < SNCH; ++j) {
        float2* p = &g_sum[((size_t)j * NDN + dn) * DI + ch];
        const float2 s = *p;
        p->x = h;                            // h_in for chunk j
        h = fmaf(h, s.x, s.y);
    }
}

__global__ void scan3_k() {
    const int gid = blockIdx.x * blockDim.x + threadIdx.x;
    const int ch4 = gid % (DI / 4);
    int r = gid / (DI / 4);
    const int j = r % SNCH; r /= SNCH;
    const int dn = r;
    const int dir = dn >> 4, n = dn & 15;
    const int ch = ch4 * 4;
    const __half2* cv = dir ? g_cv2 : g_cv1;
    __half* hs = dir ? g_hs2 : g_hs1;
    const size_t base = (size_t)n * L_ * DI + ch;
    int l = dir ? (L_ - 1 - j * SCHUNK) : j * SCHUNK;
    const int step = dir ? -1 : 1;
    const float4* hin = (const float4*)&g_sum[((size_t)j * NDN + dn) * DI + ch];
    const float4 ha = hin[0], hb = hin[1];
    float h0 = ha.x, h1 = ha.z, h2 = hb.x, h3 = hb.z;
#pragma unroll 4
    for (int i = 0; i < SCHUNK; ++i) {
        const uint4 raw = *(const uint4*)(cv + base + (size_t)l * DI);
        const float2 t0 = __half22float2(*(const __half2*)&raw.x);
        const float2 t1 = __half22float2(*(const __half2*)&raw.y);
        const float2 t2 = __half22float2(*(const __half2*)&raw.z);
        const float2 t3 = __half22float2(*(const __half2*)&raw.w);
        h0 = fmaf(h0, t0.x, t0.y);
        h1 = fmaf(h1, t1.x, t1.y);
        h2 = fmaf(h2, t2.x, t2.y);
        h3 = fmaf(h3, t3.x, t3.y);
        uint2 st;
        *(__half2*)&st.x = __floats2half2_rn(h0, h1);
        *(__half2*)&st.y = __floats2half2_rn(h2, h3);
        *(uint2*)&hs[base + (size_t)l * DI] = st;
        l += step;
    }
}

// ---------------- f16 mma.sync GEMM: 128x128x64, 3-stage, ldmatrix -----------
#define TS2     72                         // halfs per smem row (64 + 8 pad)
#define TILEH   (128 * TS2)                // halfs per operand tile
#define STAGE_B (2 * TILEH * 2)            // A+B bytes per stage = 36864
#define NSTG    3
#define DYNSMEM (NSTG * STAGE_B)           // 110592

#define EPI_CV      0
#define EPI_RES     1
#define EPI_GELU    2
#define EPI_BIASRES 3

template <int EPI>
__global__ void __launch_bounds__(256, 2)
tgemm_k(const __half* __restrict__ A1, const __half* __restrict__ B1, int K1,
        const __half* __restrict__ A2, const __half* __restrict__ B2, int K2,
        int N, const float* __restrict__ bias, const float* __restrict__ res,
        void* __restrict__ Cv) {
    extern __shared__ __half dynsmem[];
    const int tid = threadIdx.x;
    const int wid = tid >> 5, lane = tid & 31;
    const int g = lane >> 2, t = lane & 3;
    const int wm = (wid & 1) * 64, wn = (wid >> 1) * 32;
    const int bn = blockIdx.x, bm = blockIdx.y;
    const uint32_t sbase = smem_u32(dynsmem);

    // per-lane ldmatrix base offsets (bytes, within a stage)
    const int lj = lane >> 3, li = lane & 7;
    const uint32_t aoff =
        (uint32_t)(((wm + (lj & 1) * 8 + li) * TS2 + (lj >> 1) * 8) * 2);
    const uint32_t boff =
        (uint32_t)((TILEH + (wn + (lj & 1) * 8 + li) * TS2 + (lj >> 1) * 8) * 2);

    const int KT1 = K1 >> 6;
    const int KT = KT1 + (K2 >> 6);

    // hoisted per-thread global pointers (advance by 64 per k-tile)
    const int grow = tid >> 3;               // 0..31
    const int gcol = (tid & 7) * 8;          // fixed 8-half segment
    const __half* pA = A1 + (size_t)(bm * 128 + grow) * K1 + gcol;
    const __half* pB = B1 + (size_t)(bn * 128 + grow) * K1 + gcol;
    size_t str = (size_t)32 * K1;
    // smem per-thread store offsets (fixed)
    const uint32_t ssoff = (uint32_t)(grow * TS2 + gcol) * 2;

    float acc[4][4][4];
#pragma unroll
    for (int mt = 0; mt < 4; mt++)
#pragma unroll
        for (int nt = 0; nt < 4; nt++)
#pragma unroll
            for (int i = 0; i < 4; i++) acc[mt][nt][i] = 0.0f;

    int next_load = 0;
    // prologue: fully issue the first two stages (pipeline fill)
#pragma unroll
    for (int pl = 0; pl < 2; ++pl) {
        if (pl < KT) {
            if (next_load == KT1 && A2) {
                pA = A2 + (size_t)(bm * 128 + grow) * K2 + gcol;
                pB = B2 + (size_t)(bn * 128 + grow) * K2 + gcol;
                str = (size_t)32 * K2;
            }
            const uint32_t sa = sbase + (next_load % NSTG) * STAGE_B + ssoff;
#pragma unroll
            for (int i = 0; i < 4; ++i) {
                CP_ASYNC16(sa + i * (32 * TS2 * 2), pA + i * str);
                CP_ASYNC16(sa + TILEH * 2 + i * (32 * TS2 * 2), pB + i * str);
            }
            asm volatile("cp.async.commit_group;" ::: "memory");
            pA += 64; pB += 64;
            ++next_load;
        }
    }

    for (int kt = 0; kt < KT; ++kt) {
        if (kt + 1 < KT)
            asm volatile("cp.async.wait_group 1;" ::: "memory");
        else
            asm volatile("cp.async.wait_group 0;" ::: "memory");
        __syncthreads();

        // prefetch state for tile kt+2, interleaved into the MMA loop
        const bool pref = (next_load < KT);
        uint32_t spref = 0;
        if (pref) {
            if (next_load == KT1 && A2) {   // switch to second source
                pA = A2 + (size_t)(bm * 128 + grow) * K2 + gcol;
                pB = B2 + (size_t)(bn * 128 + grow) * K2 + gcol;
                str = (size_t)32 * K2;
            }
            spref = sbase + (next_load % NSTG) * STAGE_B + ssoff;
        }

        const uint32_t sa = sbase + (kt % NSTG) * STAGE_B;
        const uint32_t abase = sa + aoff;
        const uint32_t bbase = sa + boff;
#pragma unroll
        for (int ks = 0; ks < 4; ++ks) {
            const uint32_t ko = (uint32_t)(ks * 32);   // 16 halfs = 32 bytes
            uint32_t af[4][4], bf[2][4];
#pragma unroll
            for (int mt = 0; mt < 4; ++mt)
                ldsm_x4(af[mt], abase + mt * (16 * TS2 * 2) + ko);
#pragma unroll
            for (int q = 0; q < 2; ++q)
                ldsm_x4(bf[q], bbase + q * (16 * TS2 * 2) + ko);
            if (pref) {   // 2 of 8 copies per ks, in the LDSM latency shadow
                CP_ASYNC16(spref + ks * (32 * TS2 * 2), pA + ks * str);
                CP_ASYNC16(spref + TILEH * 2 + ks * (32 * TS2 * 2),
                           pB + ks * str);
            }
#pragma unroll
            for (int mt = 0; mt < 4; ++mt)
#pragma unroll
                for (int nt = 0; nt < 4; ++nt)
                    mma_f16(acc[mt][nt], af[mt],
                            bf[nt >> 1][nt & 1], bf[nt >> 1][(nt & 1) + 2]);
        }
        if (pref) {
            asm volatile("cp.async.commit_group;" ::: "memory");
            pA += 64; pB += 64;
            ++next_load;
        }
    }

    // ------------- fused epilogue (tanh.approx fast-math, paired stores) -----
#pragma unroll
    for (int mt = 0; mt < 4; ++mt) {
#pragma unroll
        for (int nt = 0; nt < 4; ++nt) {
            const int col = bn * 128 + wn + nt * 8 + 2 * t;
            const int r0 = bm * 128 + wm + mt * 16 + g;
#pragma unroll
            for (int h = 0; h < 2; ++h) {
                const int row = r0 + h * 8;
                const float v0 = acc[mt][nt][2 * h + 0];
                const float v1 = acc[mt][nt][2 * h + 1];
                const size_t idx = (size_t)row * N + col;
                if (EPI == EPI_CV) {
                    // (v0, v1) = (hidden, gate)
                    // cc = sigmoid(-gate) = 0.5 - 0.5*tanh(gate/2)   (1 MUFU)
                    // tilde_h = v0+0.5 (v0>=0) else sigmoid(v0)      (1 MUFU)
                    // v = (1-cc) * tilde_h
                    __half2* C = (__half2*)Cv;
                    const float cc = 0.5f - 0.5f * ftanh(0.5f * v1);
                    const float sn = 0.5f + 0.5f * ftanh(0.5f * v0);
                    const float tld = (v0 >= 0.0f) ? (v0 + 0.5f) : sn;
                    C[idx >> 1] = __floats2half2_rn(cc, (1.0f - cc) * tld);
                } else if (EPI == EPI_RES) {
                    float* C = (float*)Cv;
                    const float2 r = *(const float2*)&res[idx];
                    *(float2*)&C[idx] = make_float2(v0 + r.x, v1 + r.y);
                } else if (EPI == EPI_GELU) {
                    __half* C = (__half*)Cv;
                    const float2 b = *(const float2*)&bias[col];
                    *(__half2*)&C[idx] =
                        __floats2half2_rn(fgelu(v0 + b.x), fgelu(v1 + b.y));
                } else { // EPI_BIASRES
                    float* C = (float*)Cv;
                    const float2 r = *(const float2*)&res[idx];
                    const float2 b = *(const float2*)&bias[col];
                    *(float2*)&C[idx] = make_float2(v0 + b.x + r.x, v1 + b.y + r.y);
                }
            }
        }
    }
}

// ---------------- launch sequence ----------------
extern "C" void kernel_launch(void* const* d_in, const int* in_sizes, int n_in,
                              void* d_out, int out_size) {
    const float* x       = (const float*)d_in[0];
    const float* norm_w  = (const float*)d_in[1];
    const float* norm_b  = (const float*)d_in[2];
    const float* dw_w    = (const float*)d_in[3];
    const float* dw_b    = (const float*)d_in[4];
    const float* g1_whg  = (const float*)d_in[5];
    const float* g1_wout = (const float*)d_in[6];
    const float* g2_whg  = (const float*)d_in[7];
    const float* g2_wout = (const float*)d_in[8];
    const float* n2_w    = (const float*)d_in[9];
    const float* n2_b    = (const float*)d_in[10];
    const float* p1_w    = (const float*)d_in[11];
    const float* p1_b    = (const float*)d_in[12];
    const float* p2_w    = (const float*)d_in[13];
    const float* p2_b    = (const float*)d_in[14];
    float* out = (float*)d_out;

    float *hmid;
    __half2 *cv1, *cv2;
    __half *hln, *hc, *hs1, *hs2, *mn, *m1, *w1p, *w2p, *wo1t, *wo2t, *p1t, *p2t;
    cudaGetSymbolAddress((void**)&hln,  g_hln);
    cudaGetSymbolAddress((void**)&hc,   g_hc);
    cudaGetSymbolAddress((void**)&cv1,  g_cv1);
    cudaGetSymbolAddress((void**)&cv2,  g_cv2);
    cudaGetSymbolAddress((void**)&hs1,  g_hs1);
    cudaGetSymbolAddress((void**)&hs2,  g_hs2);
    cudaGetSymbolAddress((void**)&hmid, g_hmid);
    cudaGetSymbolAddress((void**)&mn,   g_mn);
    cudaGetSymbolAddress((void**)&m1,   g_m1);
    cudaGetSymbolAddress((void**)&w1p,  g_w1p);
    cudaGetSymbolAddress((void**)&w2p,  g_w2p);
    cudaGetSymbolAddress((void**)&wo1t, g_wo1t);
    cudaGetSymbolAddress((void**)&wo2t, g_wo2t);
    cudaGetSymbolAddress((void**)&p1t,  g_p1t);
    cudaGetSymbolAddress((void**)&p2t,  g_p2t);

    cudaFuncSetAttribute(tgemm_k<EPI_CV>,
                         cudaFuncAttributeMaxDynamicSharedMemorySize, DYNSMEM);
    cudaFuncSetAttribute(tgemm_k<EPI_RES>,
                         cudaFuncAttributeMaxDynamicSharedMemorySize, DYNSMEM);
    cudaFuncSetAttribute(tgemm_k<EPI_GELU>,
                         cudaFuncAttributeMaxDynamicSharedMemorySize, DYNSMEM);
    cudaFuncSetAttribute(tgemm_k<EPI_BIASRES>,
                         cudaFuncAttributeMaxDynamicSharedMemorySize, DYNSMEM);

    // 0) weight transposes (K-major) + fp16 conversion
    prep_w_k<<<256, 256>>>(g1_whg, g2_whg, g1_wout, g2_wout, p1_w, p2_w);
    // 1) LayerNorm 1 (fp16 out, feeds conv)
    ln_k<<<MTOT, 128>>>(x, norm_w, norm_b, hln);
    // 2) depthwise 3x3 conv (half2, 2 channels/thread, fp32 accum)
    dwconv_k<<<MTOT, DIM / 2>>>((const __half2*)hln, dw_w, dw_b, (__half2*)hc);
    // 3) hg GEMMs with fused (c,v) epilogue (half2 cv out)
    dim3 gHG(HG2 / 128, MTOT / 128);
    tgemm_k<EPI_CV><<<gHG, 256, DYNSMEM>>>(hc, w1p, DIM, nullptr, nullptr, 0,
                                           HG2, nullptr, nullptr, cv1);
    tgemm_k<EPI_CV><<<gHG, 256, DYNSMEM>>>(hc, w2p, DIM, nullptr, nullptr, 0,
                                           HG2, nullptr, nullptr, cv2);
    // 4) chunked parallel scans, 4 channels/thread, j-major summaries
    scan1_k<<<(NDN * SNCH * DI / 4) / 256, 256>>>();
    scan2_k<<<(NDN * DI) / 256, 256>>>();
    scan3_k<<<(NDN * SNCH * DI / 4) / 256, 256>>>();
    // 5) x1 + x2 + residual (dual-K GEMM, fp32 out)
    dim3 gD(DIM / 128, MTOT / 128);
    tgemm_k<EPI_RES><<<gD, 256, DYNSMEM>>>(hs1, wo1t, DI, hs2, wo2t, DI,
                                           DIM, nullptr, x, hmid);
    // 6) LayerNorm 2 (fp16 out, feeds MLP GEMM)
    ln_k<<<MTOT, 128>>>(hmid, n2_w, n2_b, mn);
    // 7) MLP up + bias + GELU (fp16 out)
    tgemm_k<EPI_GELU><<<gHG, 256, DYNSMEM>>>(mn, p1t, DIM, nullptr, nullptr, 0,
                                             MLPD, p1_b, nullptr, m1);
    // 8) MLP down + bias + residual -> output (fp32 exact epilogue)
    tgemm_k<EPI_BIASRES><<<gD, 256, DYNSMEM>>>(m1, p2t, MLPD, nullptr, nullptr, 0,
                                               DIM, p2_b, hmid, out);
}